// round 5
// baseline (speedup 1.0000x reference)
#include <cuda_runtime.h>
#include <math.h>

// ---------------- problem dims ----------------
#define SS    128
#define BB    64
#define EE    512
#define HH    256
#define DHH   512
#define G4H   1024
#define GD    2048
#define LDWD  2052
#define LMAXX 4
#define CC    9

#define NBE   128     // encoder persistent blocks
#define NBD   128     // decoder persistent blocks

// gate-interleaved permutations: n' -> original row n
// encoder (4H=1024 rows): n = q*256 + ni*16 + jj  where ni=n'>>6, q=(n'>>4)&3, jj=n'&15
__device__ __forceinline__ int enperm(int np) { return (((np >> 4) & 3) << 8) + ((np >> 6) << 4) + (np & 15); }
// decoder (4DH=2048 rows): n = q*512 + ni*16 + jj
__device__ __forceinline__ int deperm(int np) { return (((np >> 4) & 3) << 9) + ((np >> 6) << 4) + (np & 15); }

// ---------------- static device scratch ----------------
__device__ float g_x   [SS*BB*EE];
__device__ float g_gxf [SS*BB*G4H];      // permuted n'
__device__ float g_gxb [SS*BB*G4H];      // permuted n'
__device__ float g_h   [SS*BB*DHH];
__device__ float g_wh  [SS*BB*DHH];
__device__ float g_preS[SS*BB*GD];       // permuted n'
__device__ float g_pre0[SS*BB*GD];       // permuted n'
__device__ float g_pre1[SS*BB*GD];       // permuted n'
__device__ float g_dout[LMAXX*SS*BB*DHH];
__device__ float g_henc2[2][2*BB*HH];    // double-buffered encoder h
__device__ float g_cenc[2*BB*HH];
__device__ float g_hd  [BB*DHH];
__device__ float g_cd  [BB*DHH];
__device__ float g_ctx [BB*DHH];
__device__ float g_ghd [BB*GD];          // hd @ Wcat[:,512:]^T  (permuted n')
__device__ float g_Whhp[2*G4H*HH];       // permuted Whh rows [dir][1024][256]
__device__ float g_Wihp[2*G4H*EE];       // permuted Wih rows [dir][1024][512]
__device__ float g_bep [2*G4H];          // permuted encoder bias
__device__ float g_Wcat[GD*1024];        // permuted rows: [Wih_d[:, :512] | Whh_d]
__device__ float g_Wmid[GD*1024];        // permuted rows: Wih_d[:, 512:1536]
__device__ float g_Wprev[GD*512];        // permuted rows: Wih_d[:, 1536:2048]
__device__ float g_bdp [GD];             // permuted decoder bias
__device__ float g_ohcp[LMAXX*GD];       // permuted one-hot columns

__device__ unsigned g_barCount;
__device__ volatile unsigned g_barGen;

__device__ __forceinline__ float sigf(float x) { return 1.0f / (1.0f + __expf(-x)); }

// software grid barrier (all nb blocks co-resident)
__device__ __forceinline__ void gsync(unsigned nb) {
    __syncthreads();
    if (threadIdx.x == 0) {
        unsigned gen = g_barGen;
        __threadfence();
        if (atomicAdd(&g_barCount, 1) == nb - 1) {
            g_barCount = 0;
            __threadfence();
            g_barGen = gen + 1;
        } else {
            while (g_barGen == gen) {}
            __threadfence();
        }
    }
    __syncthreads();
}

// ---------------- prep: pack/permute weights, biases, zero states ----------------
#define PREP_TOTAL (163840 + 524288 + 1048576 + 2048 + 2097152 + 2097152 + 1048576 + 2048 + 8192)
__global__ void k_prep(const float* __restrict__ Whh_f, const float* __restrict__ Whh_b,
                       const float* __restrict__ Wih_f, const float* __restrict__ Wih_b,
                       const float* __restrict__ bih_f, const float* __restrict__ bhh_f,
                       const float* __restrict__ bih_b, const float* __restrict__ bhh_b,
                       const float* __restrict__ Wih_d, const float* __restrict__ Whh_d,
                       const float* __restrict__ bih_d, const float* __restrict__ bhh_d) {
    long long i = (long long)blockIdx.x * 256 + threadIdx.x;
    if (i < 163840) { // zero states
        if (i < 65536) g_henc2[i >> 15][i & 32767] = 0.f;
        else if (i < 98304) g_cenc[i - 65536] = 0.f;
        else if (i < 131072) g_hd[i - 98304] = 0.f;
        else g_cd[i - 131072] = 0.f;
        return;
    }
    i -= 163840;
    if (i < 524288) { // Whhp
        int dir = (int)(i >> 18), r = (int)(i & 262143);
        int np = r >> 8, k = r & 255;
        int n = enperm(np);
        g_Whhp[i] = (dir ? Whh_b : Whh_f)[n * HH + k];
        return;
    }
    i -= 524288;
    if (i < 1048576) { // Wihp
        int dir = (int)(i >> 19), r = (int)(i & 524287);
        int np = r >> 9, k = r & 511;
        int n = enperm(np);
        g_Wihp[i] = (dir ? Wih_b : Wih_f)[n * EE + k];
        return;
    }
    i -= 1048576;
    if (i < 2048) { // encoder bias
        int dir = (int)(i >> 10), np = (int)(i & 1023);
        int n = enperm(np);
        g_bep[i] = dir ? (bih_b[n] + bhh_b[n]) : (bih_f[n] + bhh_f[n]);
        return;
    }
    i -= 2048;
    if (i < 2097152) { // Wcat
        int np = (int)(i >> 10), k = (int)(i & 1023);
        int n = deperm(np);
        g_Wcat[i] = (k < 512) ? Wih_d[(size_t)n * LDWD + k] : Whh_d[(size_t)n * DHH + (k - 512)];
        return;
    }
    i -= 2097152;
    if (i < 2097152) { // Wmid
        int np = (int)(i >> 10), k = (int)(i & 1023);
        int n = deperm(np);
        g_Wmid[i] = Wih_d[(size_t)n * LDWD + 512 + k];
        return;
    }
    i -= 2097152;
    if (i < 1048576) { // Wprev
        int np = (int)(i >> 9), k = (int)(i & 511);
        int n = deperm(np);
        g_Wprev[i] = Wih_d[(size_t)n * LDWD + 1536 + k];
        return;
    }
    i -= 1048576;
    if (i < 2048) { // decoder bias
        int n = deperm((int)i);
        g_bdp[i] = bih_d[n] + bhh_d[n];
        return;
    }
    i -= 2048;
    if (i < 8192) { // one-hot columns
        int lvl = (int)(i >> 11), np = (int)(i & 2047);
        int n = deperm(np);
        g_ohcp[i] = Wih_d[(size_t)n * LDWD + GD + lvl];
        return;
    }
}

__global__ void k_embed(const int* __restrict__ seqs, const float* __restrict__ emb) {
    int m = blockIdx.x;            // m = s*64 + b
    int s0 = m >> 6, b = m & 63;
    int row = seqs[b * SS + s0];
    const float4* src = (const float4*)(emb + (size_t)row * EE);
    float4* dst = (float4*)(g_x + (size_t)m * EE);
    dst[threadIdx.x] = src[threadIdx.x];
}

// ---------------- conflict-free fp32 GEMM cores ----------------
// 64x64 tile: C = A[M,K] * W[N,K]^T. smem is k-major: lane-varying dim contiguous.
__device__ __forceinline__ void gemm64_core(float (*As)[68], float (*Ws)[68],
                                            const float* __restrict__ A, int lda,
                                            const float* __restrict__ A2,
                                            const float* __restrict__ W, int ldw,
                                            int K, int m0, int n0, float acc[4][4]) {
    int tid = threadIdx.x;
    int tm = (tid >> 4) << 2;
    int tn = (tid & 15) << 2;
    for (int k0 = 0; k0 < K; k0 += 16) {
        const float* Asrc = A;
        int kk0 = k0;
        if (A2 && k0 >= 512) { Asrc = A2; kk0 = k0 - 512; }
        #pragma unroll
        for (int i = tid; i < 1024; i += 256) {
            int r = i >> 4, k = i & 15;
            As[k][r] = Asrc[(size_t)(m0 + r) * lda + kk0 + k];
            Ws[k][r] = W[(size_t)(n0 + r) * ldw + k0 + k];
        }
        __syncthreads();
        #pragma unroll
        for (int k = 0; k < 16; k++) {
            float4 a4 = *(const float4*)&As[k][tm];
            float4 w4 = *(const float4*)&Ws[k][tn];
            acc[0][0] += a4.x * w4.x; acc[0][1] += a4.x * w4.y; acc[0][2] += a4.x * w4.z; acc[0][3] += a4.x * w4.w;
            acc[1][0] += a4.y * w4.x; acc[1][1] += a4.y * w4.y; acc[1][2] += a4.y * w4.z; acc[1][3] += a4.y * w4.w;
            acc[2][0] += a4.z * w4.x; acc[2][1] += a4.z * w4.y; acc[2][2] += a4.z * w4.z; acc[2][3] += a4.z * w4.w;
            acc[3][0] += a4.w * w4.x; acc[3][1] += a4.w * w4.y; acc[3][2] += a4.w * w4.z; acc[3][3] += a4.w * w4.w;
        }
        __syncthreads();
    }
}

// 16x64 tile: each thread owns 1 row x 4 cols
__device__ __forceinline__ void gemm16_core(float (*As2)[20], float (*Ws2)[68],
                                            const float* __restrict__ A, int lda,
                                            const float* __restrict__ W, int ldw,
                                            int K, int m0, int n0, float acc[4]) {
    int tid = threadIdx.x;
    int tr = tid >> 4;           // row 0..15
    int tn = (tid & 15) << 2;    // col*4
    for (int k0 = 0; k0 < K; k0 += 16) {
        As2[tid >> 4][tid & 15] = A[(size_t)(m0 + (tid >> 4)) * lda + k0 + (tid & 15)];
        #pragma unroll
        for (int i = tid; i < 1024; i += 256) {
            int r = i >> 4, k = i & 15;
            Ws2[k][r] = W[(size_t)(n0 + r) * ldw + k0 + k];
        }
        __syncthreads();
        #pragma unroll
        for (int kq = 0; kq < 16; kq += 4) {
            float4 a4 = *(const float4*)&As2[tr][kq];
            {
                float4 w4 = *(const float4*)&Ws2[kq + 0][tn];
                acc[0] += a4.x * w4.x; acc[1] += a4.x * w4.y; acc[2] += a4.x * w4.z; acc[3] += a4.x * w4.w;
            }
            {
                float4 w4 = *(const float4*)&Ws2[kq + 1][tn];
                acc[0] += a4.y * w4.x; acc[1] += a4.y * w4.y; acc[2] += a4.y * w4.z; acc[3] += a4.y * w4.w;
            }
            {
                float4 w4 = *(const float4*)&Ws2[kq + 2][tn];
                acc[0] += a4.z * w4.x; acc[1] += a4.z * w4.y; acc[2] += a4.z * w4.z; acc[3] += a4.z * w4.w;
            }
            {
                float4 w4 = *(const float4*)&Ws2[kq + 3][tn];
                acc[0] += a4.w * w4.x; acc[1] += a4.w * w4.y; acc[2] += a4.w * w4.z; acc[3] += a4.w * w4.w;
            }
        }
        __syncthreads();
    }
}

// generic big GEMM: C[M,N] = A*W^T (+add)(+bias). A2: second source for k>=512 (concat trick)
__global__ void __launch_bounds__(256) gemm_nt(const float* __restrict__ A, int lda,
                        const float* __restrict__ A2,
                        const float* __restrict__ W, int ldw,
                        float* __restrict__ C, int N, int K,
                        const float* __restrict__ add, const float* __restrict__ bias) {
    __shared__ __align__(16) float As[16][68];
    __shared__ __align__(16) float Ws[16][68];
    int m0 = blockIdx.x * 64, n0 = blockIdx.y * 64;
    float acc[4][4] = {};
    gemm64_core(As, Ws, A, lda, A2, W, ldw, K, m0, n0, acc);
    int tid = threadIdx.x;
    int tm = (tid >> 4) << 2, tn = (tid & 15) << 2;
    #pragma unroll
    for (int i = 0; i < 4; i++)
        #pragma unroll
        for (int j = 0; j < 4; j++) {
            size_t m = m0 + tm + i, n = n0 + tn + j;
            float v = acc[i][j];
            if (add)  v += add[m * N + n];
            if (bias) v += bias[n];
            C[m * N + n] = v;
        }
}

// ---------------- persistent encoder: fused gemm+cell, 1 barrier/step ----------------
__global__ void __launch_bounds__(256, 1) enc_persist() {
    __shared__ __align__(16) float As2[16][20];
    __shared__ __align__(16) float Ws2[16][68];
    __shared__ __align__(16) float gsm[16][68];
    int blk = blockIdx.x, tid = threadIdx.x;
    int dir = blk >> 6;
    int rem = blk & 63;
    int mi = rem >> 4;           // 0..3  (batch group of 16)
    int ni = rem & 15;           // 0..15 (n' tile of 64)
    int m0 = mi * 16, n0 = ni * 64;
    const float* W = g_Whhp + (size_t)dir * G4H * HH;
    int tr = tid >> 4, tnn = (tid & 15) << 2;
    int p = 0;
    for (int t = 0; t < SS; t++) {
        const float* A = g_henc2[p] + dir * BB * HH;
        const float* gx = dir ? (g_gxb + (size_t)(SS - 1 - t) * BB * G4H)
                              : (g_gxf + (size_t)t * BB * G4H);
        float acc[4] = {0.f, 0.f, 0.f, 0.f};
        gemm16_core(As2, Ws2, A, HH, W, HH, HH, m0, n0, acc);
        int b = m0 + tr;
        #pragma unroll
        for (int j = 0; j < 4; j++)
            gsm[tr][tnn + j] = acc[j] + gx[(size_t)b * G4H + n0 + tnn + j];
        __syncthreads();
        // cell: 16 b x 16 j
        {
            int bl = tid >> 4, jj = tid & 15;
            float gi = gsm[bl][jj], gf = gsm[bl][16 + jj], gg = gsm[bl][32 + jj], go = gsm[bl][48 + jj];
            int bb = m0 + bl, j = ni * 16 + jj;
            int ci = dir * BB * HH + bb * HH + j;
            float c = g_cenc[ci];
            c = sigf(gf) * c + sigf(gi) * tanhf(gg);
            float hn = sigf(go) * tanhf(c);
            g_cenc[ci] = c;
            g_henc2[p ^ 1][ci] = hn;
            int s0 = dir ? (SS - 1 - t) : t;
            g_h[((size_t)s0 * BB + bb) * DHH + dir * HH + j] = hn;
        }
        p ^= 1;
        gsync(NBE);
    }
}

// ---------------- persistent decoder: 2 barriers/step, fused cell ----------------
__global__ void __launch_bounds__(256, 1) dec_persist(int l0, int l1) {
    __shared__ __align__(16) float As2[16][20];
    __shared__ __align__(16) float Ws2[16][68];
    __shared__ __align__(16) float gsm[16][68];
    __shared__ __align__(16) float hd_s[DHH];
    __shared__ float sc[SS];
    __shared__ float red[128];
    int blk = blockIdx.x, tid = threadIdx.x;
    int tr = tid >> 4, tnn = (tid & 15) << 2;
    int bmi = blk >> 5, bni = blk & 31;      // phase-B tile
    for (int lvl = l0; lvl < l1; lvl++) {
        const float* pre = (lvl == 0) ? g_pre0 : g_pre1;
        const float* ohc = g_ohcp + lvl * GD;
        for (int t = 0; t < SS; t++) {
            // ===== phase A =====
            if (blk < 64) {
                // attention for batch b = blk
                int b = blk;
                for (int i = tid; i < DHH; i += 256) hd_s[i] = g_hd[b * DHH + i];
                __syncthreads();
                int warp = tid >> 5, lane = tid & 31;
                for (int s0 = warp; s0 < SS; s0 += 8) {
                    const float4* w4 = (const float4*)(g_wh + ((size_t)s0 * BB + b) * DHH);
                    const float4* h4 = (const float4*)hd_s;
                    float sum = 0.f;
                    #pragma unroll
                    for (int q = 0; q < 4; q++) {
                        float4 a = w4[lane * 4 + q];
                        float4 c = h4[lane * 4 + q];
                        sum += a.x * c.x + a.y * c.y + a.z * c.z + a.w * c.w;
                    }
                    #pragma unroll
                    for (int off = 16; off; off >>= 1) sum += __shfl_xor_sync(0xffffffffu, sum, off);
                    if (lane == 0) sc[s0] = sum;
                }
                __syncthreads();
                if (tid < 128) red[tid] = sc[tid];
                __syncthreads();
                for (int off = 64; off; off >>= 1) {
                    if (tid < off) red[tid] = fmaxf(red[tid], red[tid + off]);
                    __syncthreads();
                }
                float mx = red[0];
                __syncthreads();
                if (tid < 128) { float e = __expf(sc[tid] - mx); sc[tid] = e; red[tid] = e; }
                __syncthreads();
                for (int off = 64; off; off >>= 1) {
                    if (tid < off) red[tid] += red[tid + off];
                    __syncthreads();
                }
                float inv = 1.f / red[0];
                __syncthreads();
                for (int d = tid; d < DHH; d += 256) {
                    float acc = 0.f;
                    #pragma unroll 8
                    for (int s0 = 0; s0 < SS; s0++)
                        acc += sc[s0] * g_h[((size_t)s0 * BB + b) * DHH + d];
                    g_ctx[b * DHH + d] = acc * inv;
                }
            } else {
                // hd @ Wcat[:,512:]^T -> g_ghd, two 16x64 tiles per block
                int b2 = blk - 64;
                #pragma unroll
                for (int rep = 0; rep < 2; rep++) {
                    int tile = b2 * 2 + rep;
                    int mi = tile >> 5, ni = tile & 31;
                    float acc[4] = {0.f, 0.f, 0.f, 0.f};
                    gemm16_core(As2, Ws2, g_hd, DHH, g_Wcat + 512, 1024, DHH, mi * 16, ni * 64, acc);
                    int b = mi * 16 + tr;
                    #pragma unroll
                    for (int j = 0; j < 4; j++)
                        g_ghd[(size_t)b * GD + ni * 64 + tnn + j] = acc[j];
                    __syncthreads();
                }
            }
            gsync(NBD);
            // ===== phase B: ctx GEMM + cell, one 16x64 tile per block =====
            {
                float acc[4] = {0.f, 0.f, 0.f, 0.f};
                gemm16_core(As2, Ws2, g_ctx, DHH, g_Wcat, 1024, DHH, bmi * 16, bni * 64, acc);
                int b = bmi * 16 + tr;
                const float* prow = pre + ((size_t)t * BB + b) * GD;
                #pragma unroll
                for (int j = 0; j < 4; j++) {
                    int np = bni * 64 + tnn + j;
                    gsm[tr][tnn + j] = acc[j] + g_ghd[(size_t)b * GD + np] + prow[np] + ohc[np];
                }
                __syncthreads();
                int bl = tid >> 4, jj = tid & 15;
                float gi = gsm[bl][jj], gf = gsm[bl][16 + jj], gg = gsm[bl][32 + jj], go = gsm[bl][48 + jj];
                int bb = bmi * 16 + bl, j = bni * 16 + jj;
                int ci = bb * DHH + j;
                float c = g_cd[ci];
                c = sigf(gf) * c + sigf(gi) * tanhf(gg);
                float hn = sigf(go) * tanhf(c);
                g_cd[ci] = c;
                g_hd[ci] = hn;
                g_dout[(((size_t)lvl * SS + t) * BB + bb) * DHH + j] = hn;
            }
            gsync(NBD);
        }
    }
}

// ---------------- output projection ----------------
__global__ void out_proj(const float* __restrict__ W2, const float* __restrict__ b2,
                         float* __restrict__ out) {
    int m = blockIdx.x;
    int lane = threadIdx.x;
    const float* drow = g_dout + (size_t)m * DHH;
    float acc[CC] = {};
    for (int k = lane; k < DHH; k += 32) {
        float d = drow[k];
        #pragma unroll
        for (int c = 0; c < CC; c++) acc[c] += d * W2[c * DHH + k];
    }
    #pragma unroll
    for (int c = 0; c < CC; c++) {
        float v = acc[c];
        #pragma unroll
        for (int off = 16; off; off >>= 1) v += __shfl_xor_sync(0xffffffffu, v, off);
        if (lane == 0) out[(size_t)m * CC + c] = v + b2[c];
    }
}

// ---------------- host ----------------
static void* symaddr(const void* sym) { void* p = nullptr; cudaGetSymbolAddress(&p, sym); return p; }

extern "C" void kernel_launch(void* const* d_in, const int* in_sizes, int n_in,
                              void* d_out, int out_size) {
    const int*   seqs  = (const int*)d_in[0];
    const float* emb   = (const float*)d_in[2];
    const float* Wih_f = (const float*)d_in[3];
    const float* Whh_f = (const float*)d_in[4];
    const float* bih_f = (const float*)d_in[5];
    const float* bhh_f = (const float*)d_in[6];
    const float* Wih_b = (const float*)d_in[7];
    const float* Whh_b = (const float*)d_in[8];
    const float* bih_b = (const float*)d_in[9];
    const float* bhh_b = (const float*)d_in[10];
    const float* Wl    = (const float*)d_in[11];
    const float* Wih_d = (const float*)d_in[12];
    const float* Whh_d = (const float*)d_in[13];
    const float* bih_d = (const float*)d_in[14];
    const float* bhh_d = (const float*)d_in[15];
    const float* W2    = (const float*)d_in[16];
    const float* b2    = (const float*)d_in[17];
    float* out = (float*)d_out;

    float* px    = (float*)symaddr(g_x);
    float* pgxf  = (float*)symaddr(g_gxf);
    float* pgxb  = (float*)symaddr(g_gxb);
    float* ph    = (float*)symaddr(g_h);
    float* pwh   = (float*)symaddr(g_wh);
    float* ppreS = (float*)symaddr(g_preS);
    float* ppre0 = (float*)symaddr(g_pre0);
    float* ppre1 = (float*)symaddr(g_pre1);
    float* pdout = (float*)symaddr(g_dout);
    float* pWihp = (float*)symaddr(g_Wihp);
    float* pbep  = (float*)symaddr(g_bep);
    float* pWmid = (float*)symaddr(g_Wmid);
    float* pWprev= (float*)symaddr(g_Wprev);
    float* pbdp  = (float*)symaddr(g_bdp);

    // 0: prep (pack/permute/zero)
    k_prep<<<(PREP_TOTAL + 255) / 256, 256>>>(Whh_f, Whh_b, Wih_f, Wih_b,
                                              bih_f, bhh_f, bih_b, bhh_b,
                                              Wih_d, Whh_d, bih_d, bhh_d);
    // 1: embed
    k_embed<<<SS * BB, 128>>>(seqs, emb);
    // 2,3: encoder input GEMMs (permuted weights)
    gemm_nt<<<dim3(SS * BB / 64, G4H / 64), 256>>>(px, EE, nullptr, pWihp, EE, pgxf, G4H, EE, nullptr, pbep);
    gemm_nt<<<dim3(SS * BB / 64, G4H / 64), 256>>>(px, EE, nullptr, pWihp + G4H * EE, EE, pgxb, G4H, EE, nullptr, pbep + G4H);
    // 4: encoder recurrence
    enc_persist<<<NBE, 256>>>();
    // 5: preS = [h|x] @ Wmid^T + bd   (ncu -s 5 captures this)
    gemm_nt<<<dim3(SS * BB / 64, GD / 64), 256>>>(ph, DHH, px, pWmid, 1024, ppreS, GD, 1024, nullptr, pbdp);
    // 6: wh = h @ Wl^T
    gemm_nt<<<dim3(SS * BB / 64, DHH / 64), 256>>>(ph, DHH, nullptr, Wl, DHH, pwh, DHH, DHH, nullptr, nullptr);
    // 7: pre0 = preS + h @ Wprev^T
    gemm_nt<<<dim3(SS * BB / 64, GD / 64), 256>>>(ph, DHH, nullptr, pWprev, DHH, ppre0, GD, DHH, ppreS, nullptr);
    // 8: decoder level 0
    dec_persist<<<NBD, 256>>>(0, 1);
    // 9: pre1 = preS + dout0 @ Wprev^T
    gemm_nt<<<dim3(SS * BB / 64, GD / 64), 256>>>(pdout, DHH, nullptr, pWprev, DHH, ppre1, GD, DHH, ppreS, nullptr);
    // 10: decoder levels 1-3
    dec_persist<<<NBD, 256>>>(1, 4);
    // 11: logits
    out_proj<<<LMAXX * SS * BB, 32>>>(W2, b2, out);
}

// round 7
// speedup vs baseline: 1.0028x; 1.0028x over previous
#include <cuda_runtime.h>
#include <math.h>

// ---------------- problem dims ----------------
#define SS    128
#define BB    64
#define EE    512
#define HH    256
#define DHH   512
#define G4H   1024
#define GD    2048
#define LDWD  2052
#define LMAXX 4
#define CC    9

#define NBE   128     // encoder persistent blocks
#define NBD   128     // decoder persistent blocks

// gate-interleaved permutations: n' -> original row n
// encoder (4H=1024 rows): n = q*256 + ni*16 + jj  where ni=n'>>6, q=(n'>>4)&3, jj=n'&15
__device__ __forceinline__ int enperm(int np) { return (((np >> 4) & 3) << 8) + ((np >> 6) << 4) + (np & 15); }
// decoder (4DH=2048 rows): n = q*512 + ni*16 + jj
__device__ __forceinline__ int deperm(int np) { return (((np >> 4) & 3) << 9) + ((np >> 6) << 4) + (np & 15); }

// ---------------- static device scratch ----------------
__device__ float g_x   [SS*BB*EE];
__device__ float g_gxf [SS*BB*G4H];      // permuted n'
__device__ float g_gxb [SS*BB*G4H];      // permuted n'
__device__ float g_h   [SS*BB*DHH];
__device__ float g_wh  [SS*BB*DHH];
__device__ float g_preS[SS*BB*GD];       // permuted n'
__device__ float g_pre0[SS*BB*GD];       // permuted n'
__device__ float g_pre1[SS*BB*GD];       // permuted n'
__device__ float g_dout[LMAXX*SS*BB*DHH];
__device__ float g_henc2[2][2*BB*HH];    // double-buffered encoder h
__device__ float g_cenc[2*BB*HH];
__device__ float g_hd  [BB*DHH];
__device__ float g_cd  [BB*DHH];
__device__ float g_ctx [BB*DHH];
__device__ float g_ghd [BB*GD];          // hd @ Wcat[:,512:]^T  (permuted n')
__device__ float g_Whhp[2*G4H*HH];       // permuted Whh rows [dir][1024][256]
__device__ float g_Wihp[2*G4H*EE];       // permuted Wih rows [dir][1024][512]
__device__ float g_bep [2*G4H];          // permuted encoder bias
__device__ float g_Wcat[GD*1024];        // permuted rows: [Wih_d[:, :512] | Whh_d]
__device__ float g_Wmid[GD*1024];        // permuted rows: Wih_d[:, 512:1536]
__device__ float g_Wprev[GD*512];        // permuted rows: Wih_d[:, 1536:2048]
__device__ float g_bdp [GD];             // permuted decoder bias
__device__ float g_ohcp[LMAXX*GD];       // permuted one-hot columns

__device__ unsigned g_barCount;
__device__ volatile unsigned g_barGen;

__device__ __forceinline__ float sigf(float x) { return 1.0f / (1.0f + __expf(-x)); }

// software grid barrier (all nb blocks co-resident)
__device__ __forceinline__ void gsync(unsigned nb) {
    __syncthreads();
    if (threadIdx.x == 0) {
        unsigned gen = g_barGen;
        __threadfence();
        if (atomicAdd(&g_barCount, 1) == nb - 1) {
            g_barCount = 0;
            __threadfence();
            g_barGen = gen + 1;
        } else {
            while (g_barGen == gen) {}
            __threadfence();
        }
    }
    __syncthreads();
}

// ---------------- prep: pack/permute weights, biases, zero states ----------------
#define PREP_TOTAL (163840 + 524288 + 1048576 + 2048 + 2097152 + 2097152 + 1048576 + 2048 + 8192)
__global__ void k_prep(const float* __restrict__ Whh_f, const float* __restrict__ Whh_b,
                       const float* __restrict__ Wih_f, const float* __restrict__ Wih_b,
                       const float* __restrict__ bih_f, const float* __restrict__ bhh_f,
                       const float* __restrict__ bih_b, const float* __restrict__ bhh_b,
                       const float* __restrict__ Wih_d, const float* __restrict__ Whh_d,
                       const float* __restrict__ bih_d, const float* __restrict__ bhh_d) {
    long long i = (long long)blockIdx.x * 256 + threadIdx.x;
    if (i < 163840) { // zero states
        if (i < 65536) g_henc2[i >> 15][i & 32767] = 0.f;
        else if (i < 98304) g_cenc[i - 65536] = 0.f;
        else if (i < 131072) g_hd[i - 98304] = 0.f;
        else g_cd[i - 131072] = 0.f;
        return;
    }
    i -= 163840;
    if (i < 524288) { // Whhp
        int dir = (int)(i >> 18), r = (int)(i & 262143);
        int np = r >> 8, k = r & 255;
        int n = enperm(np);
        g_Whhp[i] = (dir ? Whh_b : Whh_f)[n * HH + k];
        return;
    }
    i -= 524288;
    if (i < 1048576) { // Wihp
        int dir = (int)(i >> 19), r = (int)(i & 524287);
        int np = r >> 9, k = r & 511;
        int n = enperm(np);
        g_Wihp[i] = (dir ? Wih_b : Wih_f)[n * EE + k];
        return;
    }
    i -= 1048576;
    if (i < 2048) { // encoder bias
        int dir = (int)(i >> 10), np = (int)(i & 1023);
        int n = enperm(np);
        g_bep[i] = dir ? (bih_b[n] + bhh_b[n]) : (bih_f[n] + bhh_f[n]);
        return;
    }
    i -= 2048;
    if (i < 2097152) { // Wcat
        int np = (int)(i >> 10), k = (int)(i & 1023);
        int n = deperm(np);
        g_Wcat[i] = (k < 512) ? Wih_d[(size_t)n * LDWD + k] : Whh_d[(size_t)n * DHH + (k - 512)];
        return;
    }
    i -= 2097152;
    if (i < 2097152) { // Wmid
        int np = (int)(i >> 10), k = (int)(i & 1023);
        int n = deperm(np);
        g_Wmid[i] = Wih_d[(size_t)n * LDWD + 512 + k];
        return;
    }
    i -= 2097152;
    if (i < 1048576) { // Wprev
        int np = (int)(i >> 9), k = (int)(i & 511);
        int n = deperm(np);
        g_Wprev[i] = Wih_d[(size_t)n * LDWD + 1536 + k];
        return;
    }
    i -= 1048576;
    if (i < 2048) { // decoder bias
        int n = deperm((int)i);
        g_bdp[i] = bih_d[n] + bhh_d[n];
        return;
    }
    i -= 2048;
    if (i < 8192) { // one-hot columns
        int lvl = (int)(i >> 11), np = (int)(i & 2047);
        int n = deperm(np);
        g_ohcp[i] = Wih_d[(size_t)n * LDWD + GD + lvl];
        return;
    }
}

__global__ void k_embed(const int* __restrict__ seqs, const float* __restrict__ emb) {
    int m = blockIdx.x;            // m = s*64 + b
    int s0 = m >> 6, b = m & 63;
    int row = seqs[b * SS + s0];
    const float4* src = (const float4*)(emb + (size_t)row * EE);
    float4* dst = (float4*)(g_x + (size_t)m * EE);
    dst[threadIdx.x] = src[threadIdx.x];
}

// ---------------- conflict-free fp32 GEMM cores ----------------
// 64x64 tile: C = A[M,K] * W[N,K]^T. smem is k-major: lane-varying dim contiguous.
__device__ __forceinline__ void gemm64_core(float (*As)[68], float (*Ws)[68],
                                            const float* __restrict__ A, int lda,
                                            const float* __restrict__ A2,
                                            const float* __restrict__ W, int ldw,
                                            int K, int m0, int n0, float acc[4][4]) {
    int tid = threadIdx.x;
    int tm = (tid >> 4) << 2;
    int tn = (tid & 15) << 2;
    for (int k0 = 0; k0 < K; k0 += 16) {
        const float* Asrc = A;
        int kk0 = k0;
        if (A2 && k0 >= 512) { Asrc = A2; kk0 = k0 - 512; }
        #pragma unroll
        for (int i = tid; i < 1024; i += 256) {
            int r = i >> 4, k = i & 15;
            As[k][r] = Asrc[(size_t)(m0 + r) * lda + kk0 + k];
            Ws[k][r] = W[(size_t)(n0 + r) * ldw + k0 + k];
        }
        __syncthreads();
        #pragma unroll
        for (int k = 0; k < 16; k++) {
            float4 a4 = *(const float4*)&As[k][tm];
            float4 w4 = *(const float4*)&Ws[k][tn];
            acc[0][0] += a4.x * w4.x; acc[0][1] += a4.x * w4.y; acc[0][2] += a4.x * w4.z; acc[0][3] += a4.x * w4.w;
            acc[1][0] += a4.y * w4.x; acc[1][1] += a4.y * w4.y; acc[1][2] += a4.y * w4.z; acc[1][3] += a4.y * w4.w;
            acc[2][0] += a4.z * w4.x; acc[2][1] += a4.z * w4.y; acc[2][2] += a4.z * w4.z; acc[2][3] += a4.z * w4.w;
            acc[3][0] += a4.w * w4.x; acc[3][1] += a4.w * w4.y; acc[3][2] += a4.w * w4.z; acc[3][3] += a4.w * w4.w;
        }
        __syncthreads();
    }
}

// 16x64 tile: each thread owns 1 row x 4 cols
__device__ __forceinline__ void gemm16_core(float (*As2)[20], float (*Ws2)[68],
                                            const float* __restrict__ A, int lda,
                                            const float* __restrict__ W, int ldw,
                                            int K, int m0, int n0, float acc[4]) {
    int tid = threadIdx.x;
    int tr = tid >> 4;           // row 0..15
    int tn = (tid & 15) << 2;    // col*4
    for (int k0 = 0; k0 < K; k0 += 16) {
        As2[tid >> 4][tid & 15] = A[(size_t)(m0 + (tid >> 4)) * lda + k0 + (tid & 15)];
        #pragma unroll
        for (int i = tid; i < 1024; i += 256) {
            int r = i >> 4, k = i & 15;
            Ws2[k][r] = W[(size_t)(n0 + r) * ldw + k0 + k];
        }
        __syncthreads();
        #pragma unroll
        for (int kq = 0; kq < 16; kq += 4) {
            float4 a4 = *(const float4*)&As2[tr][kq];
            {
                float4 w4 = *(const float4*)&Ws2[kq + 0][tn];
                acc[0] += a4.x * w4.x; acc[1] += a4.x * w4.y; acc[2] += a4.x * w4.z; acc[3] += a4.x * w4.w;
            }
            {
                float4 w4 = *(const float4*)&Ws2[kq + 1][tn];
                acc[0] += a4.y * w4.x; acc[1] += a4.y * w4.y; acc[2] += a4.y * w4.z; acc[3] += a4.y * w4.w;
            }
            {
                float4 w4 = *(const float4*)&Ws2[kq + 2][tn];
                acc[0] += a4.z * w4.x; acc[1] += a4.z * w4.y; acc[2] += a4.z * w4.z; acc[3] += a4.z * w4.w;
            }
            {
                float4 w4 = *(const float4*)&Ws2[kq + 3][tn];
                acc[0] += a4.w * w4.x; acc[1] += a4.w * w4.y; acc[2] += a4.w * w4.z; acc[3] += a4.w * w4.w;
            }
        }
        __syncthreads();
    }
}

// generic big GEMM: C[M,N] = A*W^T (+add)(+bias). A2: second source for k>=512 (concat trick)
__global__ void __launch_bounds__(256) gemm_nt(const float* __restrict__ A, int lda,
                        const float* __restrict__ A2,
                        const float* __restrict__ W, int ldw,
                        float* __restrict__ C, int N, int K,
                        const float* __restrict__ add, const float* __restrict__ bias) {
    __shared__ __align__(16) float As[16][68];
    __shared__ __align__(16) float Ws[16][68];
    int m0 = blockIdx.x * 64, n0 = blockIdx.y * 64;
    float acc[4][4] = {};
    gemm64_core(As, Ws, A, lda, A2, W, ldw, K, m0, n0, acc);
    int tid = threadIdx.x;
    int tm = (tid >> 4) << 2, tn = (tid & 15) << 2;
    #pragma unroll
    for (int i = 0; i < 4; i++)
        #pragma unroll
        for (int j = 0; j < 4; j++) {
            size_t m = m0 + tm + i, n = n0 + tn + j;
            float v = acc[i][j];
            if (add)  v += add[m * N + n];
            if (bias) v += bias[n];
            C[m * N + n] = v;
        }
}

// ---------------- persistent encoder: fused gemm+cell, 1 barrier/step ----------------
__global__ void __launch_bounds__(256, 1) enc_persist() {
    __shared__ __align__(16) float As2[16][20];
    __shared__ __align__(16) float Ws2[16][68];
    __shared__ __align__(16) float gsm[16][68];
    int blk = blockIdx.x, tid = threadIdx.x;
    int dir = blk >> 6;
    int rem = blk & 63;
    int mi = rem >> 4;           // 0..3  (batch group of 16)
    int ni = rem & 15;           // 0..15 (n' tile of 64)
    int m0 = mi * 16, n0 = ni * 64;
    const float* W = g_Whhp + (size_t)dir * G4H * HH;
    int tr = tid >> 4, tnn = (tid & 15) << 2;
    int p = 0;
    for (int t = 0; t < SS; t++) {
        const float* A = g_henc2[p] + dir * BB * HH;
        const float* gx = dir ? (g_gxb + (size_t)(SS - 1 - t) * BB * G4H)
                              : (g_gxf + (size_t)t * BB * G4H);
        float acc[4] = {0.f, 0.f, 0.f, 0.f};
        gemm16_core(As2, Ws2, A, HH, W, HH, HH, m0, n0, acc);
        int b = m0 + tr;
        #pragma unroll
        for (int j = 0; j < 4; j++)
            gsm[tr][tnn + j] = acc[j] + gx[(size_t)b * G4H + n0 + tnn + j];
        __syncthreads();
        // cell: 16 b x 16 j
        {
            int bl = tid >> 4, jj = tid & 15;
            float gi = gsm[bl][jj], gf = gsm[bl][16 + jj], gg = gsm[bl][32 + jj], go = gsm[bl][48 + jj];
            int bb = m0 + bl, j = ni * 16 + jj;
            int ci = dir * BB * HH + bb * HH + j;
            float c = g_cenc[ci];
            c = sigf(gf) * c + sigf(gi) * tanhf(gg);
            float hn = sigf(go) * tanhf(c);
            g_cenc[ci] = c;
            g_henc2[p ^ 1][ci] = hn;
            int s0 = dir ? (SS - 1 - t) : t;
            g_h[((size_t)s0 * BB + bb) * DHH + dir * HH + j] = hn;
        }
        p ^= 1;
        gsync(NBE);
    }
}

// ---------------- persistent decoder: 2 barriers/step, fused cell ----------------
__global__ void __launch_bounds__(256, 1) dec_persist(int l0, int l1) {
    __shared__ __align__(16) float As2[16][20];
    __shared__ __align__(16) float Ws2[16][68];
    __shared__ __align__(16) float gsm[16][68];
    __shared__ __align__(16) float hd_s[DHH];
    __shared__ float sc[SS];
    __shared__ float red[128];
    int blk = blockIdx.x, tid = threadIdx.x;
    int tr = tid >> 4, tnn = (tid & 15) << 2;
    int bmi = blk >> 5, bni = blk & 31;      // phase-B tile
    for (int lvl = l0; lvl < l1; lvl++) {
        const float* pre = (lvl == 0) ? g_pre0 : g_pre1;
        const float* ohc = g_ohcp + lvl * GD;
        for (int t = 0; t < SS; t++) {
            // ===== phase A =====
            if (blk < 64) {
                // attention for batch b = blk
                int b = blk;
                for (int i = tid; i < DHH; i += 256) hd_s[i] = g_hd[b * DHH + i];
                __syncthreads();
                int warp = tid >> 5, lane = tid & 31;
                for (int s0 = warp; s0 < SS; s0 += 8) {
                    const float4* w4 = (const float4*)(g_wh + ((size_t)s0 * BB + b) * DHH);
                    const float4* h4 = (const float4*)hd_s;
                    float sum = 0.f;
                    #pragma unroll
                    for (int q = 0; q < 4; q++) {
                        float4 a = w4[lane * 4 + q];
                        float4 c = h4[lane * 4 + q];
                        sum += a.x * c.x + a.y * c.y + a.z * c.z + a.w * c.w;
                    }
                    #pragma unroll
                    for (int off = 16; off; off >>= 1) sum += __shfl_xor_sync(0xffffffffu, sum, off);
                    if (lane == 0) sc[s0] = sum;
                }
                __syncthreads();
                if (tid < 128) red[tid] = sc[tid];
                __syncthreads();
                for (int off = 64; off; off >>= 1) {
                    if (tid < off) red[tid] = fmaxf(red[tid], red[tid + off]);
                    __syncthreads();
                }
                float mx = red[0];
                __syncthreads();
                if (tid < 128) { float e = __expf(sc[tid] - mx); sc[tid] = e; red[tid] = e; }
                __syncthreads();
                for (int off = 64; off; off >>= 1) {
                    if (tid < off) red[tid] += red[tid + off];
                    __syncthreads();
                }
                float inv = 1.f / red[0];
                __syncthreads();
                for (int d = tid; d < DHH; d += 256) {
                    float acc = 0.f;
                    #pragma unroll 8
                    for (int s0 = 0; s0 < SS; s0++)
                        acc += sc[s0] * g_h[((size_t)s0 * BB + b) * DHH + d];
                    g_ctx[b * DHH + d] = acc * inv;
                }
            } else {
                // hd @ Wcat[:,512:]^T -> g_ghd, two 16x64 tiles per block
                int b2 = blk - 64;
                #pragma unroll
                for (int rep = 0; rep < 2; rep++) {
                    int tile = b2 * 2 + rep;
                    int mi = tile >> 5, ni = tile & 31;
                    float acc[4] = {0.f, 0.f, 0.f, 0.f};
                    gemm16_core(As2, Ws2, g_hd, DHH, g_Wcat + 512, 1024, DHH, mi * 16, ni * 64, acc);
                    int b = mi * 16 + tr;
                    #pragma unroll
                    for (int j = 0; j < 4; j++)
                        g_ghd[(size_t)b * GD + ni * 64 + tnn + j] = acc[j];
                    __syncthreads();
                }
            }
            gsync(NBD);
            // ===== phase B: ctx GEMM + cell, one 16x64 tile per block =====
            {
                float acc[4] = {0.f, 0.f, 0.f, 0.f};
                gemm16_core(As2, Ws2, g_ctx, DHH, g_Wcat, 1024, DHH, bmi * 16, bni * 64, acc);
                int b = bmi * 16 + tr;
                const float* prow = pre + ((size_t)t * BB + b) * GD;
                #pragma unroll
                for (int j = 0; j < 4; j++) {
                    int np = bni * 64 + tnn + j;
                    gsm[tr][tnn + j] = acc[j] + g_ghd[(size_t)b * GD + np] + prow[np] + ohc[np];
                }
                __syncthreads();
                int bl = tid >> 4, jj = tid & 15;
                float gi = gsm[bl][jj], gf = gsm[bl][16 + jj], gg = gsm[bl][32 + jj], go = gsm[bl][48 + jj];
                int bb = bmi * 16 + bl, j = bni * 16 + jj;
                int ci = bb * DHH + j;
                float c = g_cd[ci];
                c = sigf(gf) * c + sigf(gi) * tanhf(gg);
                float hn = sigf(go) * tanhf(c);
                g_cd[ci] = c;
                g_hd[ci] = hn;
                g_dout[(((size_t)lvl * SS + t) * BB + bb) * DHH + j] = hn;
            }
            gsync(NBD);
        }
    }
}

// ---------------- output projection ----------------
__global__ void out_proj(const float* __restrict__ W2, const float* __restrict__ b2,
                         float* __restrict__ out) {
    int m = blockIdx.x;
    int lane = threadIdx.x;
    const float* drow = g_dout + (size_t)m * DHH;
    float acc[CC] = {};
    for (int k = lane; k < DHH; k += 32) {
        float d = drow[k];
        #pragma unroll
        for (int c = 0; c < CC; c++) acc[c] += d * W2[c * DHH + k];
    }
    #pragma unroll
    for (int c = 0; c < CC; c++) {
        float v = acc[c];
        #pragma unroll
        for (int off = 16; off; off >>= 1) v += __shfl_xor_sync(0xffffffffu, v, off);
        if (lane == 0) out[(size_t)m * CC + c] = v + b2[c];
    }
}

// ---------------- host ----------------
static void* symaddr(const void* sym) { void* p = nullptr; cudaGetSymbolAddress(&p, sym); return p; }

extern "C" void kernel_launch(void* const* d_in, const int* in_sizes, int n_in,
                              void* d_out, int out_size) {
    const int*   seqs  = (const int*)d_in[0];
    const float* emb   = (const float*)d_in[2];
    const float* Wih_f = (const float*)d_in[3];
    const float* Whh_f = (const float*)d_in[4];
    const float* bih_f = (const float*)d_in[5];
    const float* bhh_f = (const float*)d_in[6];
    const float* Wih_b = (const float*)d_in[7];
    const float* Whh_b = (const float*)d_in[8];
    const float* bih_b = (const float*)d_in[9];
    const float* bhh_b = (const float*)d_in[10];
    const float* Wl    = (const float*)d_in[11];
    const float* Wih_d = (const float*)d_in[12];
    const float* Whh_d = (const float*)d_in[13];
    const float* bih_d = (const float*)d_in[14];
    const float* bhh_d = (const float*)d_in[15];
    const float* W2    = (const float*)d_in[16];
    const float* b2    = (const float*)d_in[17];
    float* out = (float*)d_out;

    float* px    = (float*)symaddr(g_x);
    float* pgxf  = (float*)symaddr(g_gxf);
    float* pgxb  = (float*)symaddr(g_gxb);
    float* ph    = (float*)symaddr(g_h);
    float* pwh   = (float*)symaddr(g_wh);
    float* ppreS = (float*)symaddr(g_preS);
    float* ppre0 = (float*)symaddr(g_pre0);
    float* ppre1 = (float*)symaddr(g_pre1);
    float* pdout = (float*)symaddr(g_dout);
    float* pWihp = (float*)symaddr(g_Wihp);
    float* pbep  = (float*)symaddr(g_bep);
    float* pWmid = (float*)symaddr(g_Wmid);
    float* pWprev= (float*)symaddr(g_Wprev);
    float* pbdp  = (float*)symaddr(g_bdp);

    // 0: prep (pack/permute/zero)
    k_prep<<<(PREP_TOTAL + 255) / 256, 256>>>(Whh_f, Whh_b, Wih_f, Wih_b,
                                              bih_f, bhh_f, bih_b, bhh_b,
                                              Wih_d, Whh_d, bih_d, bhh_d);
    // 1: embed
    k_embed<<<SS * BB, 128>>>(seqs, emb);
    // 2,3: encoder input GEMMs (permuted weights)
    gemm_nt<<<dim3(SS * BB / 64, G4H / 64), 256>>>(px, EE, nullptr, pWihp, EE, pgxf, G4H, EE, nullptr, pbep);
    gemm_nt<<<dim3(SS * BB / 64, G4H / 64), 256>>>(px, EE, nullptr, pWihp + G4H * EE, EE, pgxb, G4H, EE, nullptr, pbep + G4H);
    // 4: encoder recurrence
    enc_persist<<<NBE, 256>>>();
    // 5: preS = [h|x] @ Wmid^T + bd   (ncu -s 5 captures this)
    gemm_nt<<<dim3(SS * BB / 64, GD / 64), 256>>>(ph, DHH, px, pWmid, 1024, ppreS, GD, 1024, nullptr, pbdp);
    // 6: wh = h @ Wl^T
    gemm_nt<<<dim3(SS * BB / 64, DHH / 64), 256>>>(ph, DHH, nullptr, Wl, DHH, pwh, DHH, DHH, nullptr, nullptr);
    // 7: pre0 = preS + h @ Wprev^T
    gemm_nt<<<dim3(SS * BB / 64, GD / 64), 256>>>(ph, DHH, nullptr, pWprev, DHH, ppre0, GD, DHH, ppreS, nullptr);
    // 8: decoder level 0
    dec_persist<<<NBD, 256>>>(0, 1);
    // 9: pre1 = preS + dout0 @ Wprev^T
    gemm_nt<<<dim3(SS * BB / 64, GD / 64), 256>>>(pdout, DHH, nullptr, pWprev, DHH, ppre1, GD, DHH, ppreS, nullptr);
    // 10: decoder levels 1-3
    dec_persist<<<NBD, 256>>>(1, 4);
    // 11: logits
    out_proj<<<LMAXX * SS * BB, 32>>>(W2, b2, out);
}

// round 9
// speedup vs baseline: 2.3125x; 2.3060x over previous
#include <cuda_runtime.h>
#include <math.h>

// ---------------- problem dims ----------------
#define SS    128
#define BB    64
#define EE    512
#define HH    256
#define DHH   512
#define G4H   1024
#define GD    2048
#define LDWD  2052
#define LMAXX 4
#define CC    9

#define NBE   128
#define NBD   128

// gate-locality permutations: each block owns all 4 gates of 4 hidden units.
// encoder: n' = ublk*16 + q*4 + uu  ->  n = q*256 + ublk*4 + uu   (ublk 0..63)
__device__ __forceinline__ int enperm(int np) { return (((np >> 2) & 3) << 8) + ((np >> 4) << 2) + (np & 3); }
// decoder: n' = blk*16 + q*4 + uu   ->  n = q*512 + blk*4 + uu    (blk 0..127)
__device__ __forceinline__ int deperm(int np) { return (((np >> 2) & 3) << 9) + ((np >> 4) << 2) + (np & 3); }

// ---------------- static device scratch ----------------
__device__ float g_x   [SS*BB*EE];
__device__ float g_gxf [SS*BB*G4H];      // [t][b][n'] permuted
__device__ float g_gxb [SS*BB*G4H];
__device__ float g_h   [SS*BB*DHH];
__device__ float g_wh  [SS*BB*DHH];
__device__ float g_preS[SS*BB*GD];       // [t][b][n'] permuted
__device__ float g_pre0[SS*BB*GD];
__device__ float g_pre1[SS*BB*GD];
__device__ float g_dout[LMAXX*SS*BB*DHH];
__device__ float g_hencT[2*2*HH*BB];     // [p][dir][u][b] k-major encoder h
__device__ float g_cencT[2*HH*BB];       // [dir][u][b]
__device__ float g_hd  [BB*DHH];         // [b][u]  (attention)
__device__ float g_hdT [DHH*BB];         // [u][b]  (GEMM staging)
__device__ float g_cdT [DHH*BB];
__device__ float g_ctxT[DHH*BB];         // [d][b]
__device__ float g_Whhp[2*G4H*HH];       // permuted rows [dir][n'][k]
__device__ float g_Wihp[2*G4H*EE];
__device__ float g_bep [2*G4H];
__device__ float g_Wcat[GD*1024];        // permuted rows: [Wih_d[:, :512] | Whh_d]
__device__ float g_Wmid[GD*1024];        // permuted rows: Wih_d[:, 512:1536]
__device__ float g_Wprev[GD*DHH];        // permuted rows: Wih_d[:, 1536:2048]
__device__ float g_bdp [GD];
__device__ float g_ohcp[LMAXX*GD];

__device__ unsigned g_barCount;
__device__ volatile unsigned g_barGen;

__device__ __forceinline__ float sigf(float x) { return 1.0f / (1.0f + __expf(-x)); }

__device__ __forceinline__ void gsync(unsigned nb) {
    __syncthreads();
    if (threadIdx.x == 0) {
        unsigned gen = g_barGen;
        __threadfence();
        if (atomicAdd(&g_barCount, 1) == nb - 1) {
            g_barCount = 0;
            __threadfence();
            g_barGen = gen + 1;
        } else {
            while (g_barGen == gen) {}
            __threadfence();
        }
    }
    __syncthreads();
}

// ---------------- prep: permute weights, fold biases, zero states ----------------
#define Z_TOTAL 196608
#define PREP_TOTAL (Z_TOTAL + 524288 + 1048576 + 2048 + 2097152 + 2097152 + 1048576 + 2048 + 8192)
__global__ void k_prep(const float* __restrict__ Whh_f, const float* __restrict__ Whh_b,
                       const float* __restrict__ Wih_f, const float* __restrict__ Wih_b,
                       const float* __restrict__ bih_f, const float* __restrict__ bhh_f,
                       const float* __restrict__ bih_b, const float* __restrict__ bhh_b,
                       const float* __restrict__ Wih_d, const float* __restrict__ Whh_d,
                       const float* __restrict__ bih_d, const float* __restrict__ bhh_d) {
    long long i = (long long)blockIdx.x * 256 + threadIdx.x;
    if (i < Z_TOTAL) {
        if (i < 65536) g_hencT[i] = 0.f;
        else if (i < 98304) g_cencT[i - 65536] = 0.f;
        else if (i < 131072) g_hd[i - 98304] = 0.f;
        else if (i < 163840) g_hdT[i - 131072] = 0.f;
        else g_cdT[i - 163840] = 0.f;
        return;
    }
    i -= Z_TOTAL;
    if (i < 524288) { // Whhp
        int dir = (int)(i >> 18), r = (int)(i & 262143);
        int np = r >> 8, k = r & 255;
        int n = enperm(np);
        g_Whhp[i] = (dir ? Whh_b : Whh_f)[n * HH + k];
        return;
    }
    i -= 524288;
    if (i < 1048576) { // Wihp
        int dir = (int)(i >> 19), r = (int)(i & 524287);
        int np = r >> 9, k = r & 511;
        int n = enperm(np);
        g_Wihp[i] = (dir ? Wih_b : Wih_f)[n * EE + k];
        return;
    }
    i -= 1048576;
    if (i < 2048) { // encoder bias
        int dir = (int)(i >> 10), np = (int)(i & 1023);
        int n = enperm(np);
        g_bep[i] = dir ? (bih_b[n] + bhh_b[n]) : (bih_f[n] + bhh_f[n]);
        return;
    }
    i -= 2048;
    if (i < 2097152) { // Wcat
        int np = (int)(i >> 10), k = (int)(i & 1023);
        int n = deperm(np);
        g_Wcat[i] = (k < 512) ? Wih_d[(size_t)n * LDWD + k] : Whh_d[(size_t)n * DHH + (k - 512)];
        return;
    }
    i -= 2097152;
    if (i < 2097152) { // Wmid
        int np = (int)(i >> 10), k = (int)(i & 1023);
        int n = deperm(np);
        g_Wmid[i] = Wih_d[(size_t)n * LDWD + 512 + k];
        return;
    }
    i -= 2097152;
    if (i < 1048576) { // Wprev
        int np = (int)(i >> 9), k = (int)(i & 511);
        int n = deperm(np);
        g_Wprev[i] = Wih_d[(size_t)n * LDWD + 1536 + k];
        return;
    }
    i -= 1048576;
    if (i < 2048) { // decoder bias
        int n = deperm((int)i);
        g_bdp[i] = bih_d[n] + bhh_d[n];
        return;
    }
    i -= 2048;
    if (i < 8192) { // one-hot columns
        int lvl = (int)(i >> 11), np = (int)(i & 2047);
        int n = deperm(np);
        g_ohcp[i] = Wih_d[(size_t)n * LDWD + GD + lvl];
        return;
    }
}

__global__ void k_embed(const int* __restrict__ seqs, const float* __restrict__ emb) {
    int m = blockIdx.x;            // m = s*64 + b
    int s0 = m >> 6, b = m & 63;
    int row = seqs[b * SS + s0];
    const float4* src = (const float4*)(emb + (size_t)row * EE);
    float4* dst = (float4*)(g_x + (size_t)m * EE);
    dst[threadIdx.x] = src[threadIdx.x];
}

// ---------------- precompute GEMM (conflict-free, measured ~30TF/s) ----------------
__global__ void __launch_bounds__(256) gemm_nt(const float* __restrict__ A, int lda,
                        const float* __restrict__ A2,
                        const float* __restrict__ W, int ldw,
                        float* __restrict__ C, int N, int K,
                        const float* __restrict__ add, const float* __restrict__ bias) {
    __shared__ __align__(16) float As[16][68];
    __shared__ __align__(16) float Ws[16][68];
    int m0 = blockIdx.x * 64, n0 = blockIdx.y * 64;
    int tid = threadIdx.x;
    int tm = (tid >> 4) << 2, tn = (tid & 15) << 2;
    float acc[4][4] = {};
    for (int k0 = 0; k0 < K; k0 += 16) {
        const float* Asrc = A;
        int kk0 = k0;
        if (A2 && k0 >= 512) { Asrc = A2; kk0 = k0 - 512; }
        #pragma unroll
        for (int i = tid; i < 1024; i += 256) {
            int r = i >> 4, k = i & 15;
            As[k][r] = Asrc[(size_t)(m0 + r) * lda + kk0 + k];
            Ws[k][r] = W[(size_t)(n0 + r) * ldw + k0 + k];
        }
        __syncthreads();
        #pragma unroll
        for (int k = 0; k < 16; k++) {
            float4 a4 = *(const float4*)&As[k][tm];
            float4 w4 = *(const float4*)&Ws[k][tn];
            acc[0][0] += a4.x * w4.x; acc[0][1] += a4.x * w4.y; acc[0][2] += a4.x * w4.z; acc[0][3] += a4.x * w4.w;
            acc[1][0] += a4.y * w4.x; acc[1][1] += a4.y * w4.y; acc[1][2] += a4.y * w4.z; acc[1][3] += a4.y * w4.w;
            acc[2][0] += a4.z * w4.x; acc[2][1] += a4.z * w4.y; acc[2][2] += a4.z * w4.z; acc[2][3] += a4.z * w4.w;
            acc[3][0] += a4.w * w4.x; acc[3][1] += a4.w * w4.y; acc[3][2] += a4.w * w4.z; acc[3][3] += a4.w * w4.w;
        }
        __syncthreads();
    }
    #pragma unroll
    for (int i = 0; i < 4; i++)
        #pragma unroll
        for (int j = 0; j < 4; j++) {
            size_t m = m0 + tm + i, n = n0 + tn + j;
            float v = acc[i][j];
            if (add)  v += add[m * N + n];
            if (bias) v += bias[n];
            C[m * N + n] = v;
        }
}

// ---------------- W-resident GEMM half: acc += AT-slice @ Wsm-slice ----------------
// AT: [Kh=chunks*64][64] k-major activations; Wsm: [k][20] (row r at +r, float4 at q*4)
template<int CHUNKS>
__device__ __forceinline__ void wres_gemm(const float* __restrict__ AT,
                                          const float* __restrict__ Wsm, int kbase,
                                          float (*Asm)[64],
                                          int q, int b, int kl, int b4,
                                          float& a0, float& a1, float& a2, float& a3) {
    float4 pf0 = *(const float4*)&AT[(size_t)(kl     ) * 64 + b4];
    float4 pf1 = *(const float4*)&AT[(size_t)(kl + 16) * 64 + b4];
    float4 pf2 = *(const float4*)&AT[(size_t)(kl + 32) * 64 + b4];
    float4 pf3 = *(const float4*)&AT[(size_t)(kl + 48) * 64 + b4];
    for (int c = 0; c < CHUNKS; c++) {
        __syncthreads();
        *(float4*)&Asm[kl     ][b4] = pf0;
        *(float4*)&Asm[kl + 16][b4] = pf1;
        *(float4*)&Asm[kl + 32][b4] = pf2;
        *(float4*)&Asm[kl + 48][b4] = pf3;
        __syncthreads();
        if (c < CHUNKS - 1) {
            const float* src = AT + (size_t)(c + 1) * 64 * 64;
            pf0 = *(const float4*)&src[(size_t)(kl     ) * 64 + b4];
            pf1 = *(const float4*)&src[(size_t)(kl + 16) * 64 + b4];
            pf2 = *(const float4*)&src[(size_t)(kl + 32) * 64 + b4];
            pf3 = *(const float4*)&src[(size_t)(kl + 48) * 64 + b4];
        }
        const float* wp = Wsm + (size_t)(kbase + c * 64) * 20 + q * 4;
        #pragma unroll 16
        for (int k = 0; k < 64; k++) {
            float a = Asm[k][b];
            float4 w = *(const float4*)&wp[k * 20];
            a0 += a * w.x; a1 += a * w.y; a2 += a * w.z; a3 += a * w.w;
        }
    }
}

// ---------------- persistent encoder ----------------
__global__ void __launch_bounds__(256, 1) enc_persist() {
    __shared__ __align__(16) float Wsm[HH * 20];     // 20KB
    __shared__ __align__(16) float Asm[64][64];      // 16KB
    __shared__ float gsm[16][64];                    // 4KB
    int blk = blockIdx.x, tid = threadIdx.x;
    int dir = blk >> 6, ub = blk & 63;
    for (int i = tid; i < 16 * HH; i += 256) {
        int r = i >> 8, k = i & 255;
        Wsm[k * 20 + r] = g_Whhp[((size_t)dir * G4H + ub * 16 + r) * HH + k];
    }
    __syncthreads();
    int q = tid >> 6, b = tid & 63;
    int kl = tid >> 4, b4 = (tid & 15) << 2;
    int uu = tid >> 6;
    int p = 0;
    for (int t = 0; t < SS; t++) {
        const float* AT = g_hencT + ((size_t)p * 2 + dir) * HH * BB;
        float a0 = 0.f, a1 = 0.f, a2 = 0.f, a3 = 0.f;
        wres_gemm<4>(AT, Wsm, 0, Asm, q, b, kl, b4, a0, a1, a2, a3);
        int s0 = dir ? (SS - 1 - t) : t;
        float4 g4 = *(const float4*)((dir ? g_gxb : g_gxf) + ((size_t)s0 * BB + b) * G4H + ub * 16 + q * 4);
        gsm[q * 4 + 0][b] = a0 + g4.x;
        gsm[q * 4 + 1][b] = a1 + g4.y;
        gsm[q * 4 + 2][b] = a2 + g4.z;
        gsm[q * 4 + 3][b] = a3 + g4.w;
        __syncthreads();
        {
            float gi = gsm[0 + uu][b], gf = gsm[4 + uu][b], gg = gsm[8 + uu][b], go = gsm[12 + uu][b];
            int u = ub * 4 + uu;
            size_t ci = ((size_t)dir * HH + u) * BB + b;
            float c = g_cencT[ci];
            c = sigf(gf) * c + sigf(gi) * tanhf(gg);
            float hn = sigf(go) * tanhf(c);
            g_cencT[ci] = c;
            g_hencT[((size_t)(p ^ 1) * 2 + dir) * HH * BB + (size_t)u * BB + b] = hn;
            g_h[((size_t)s0 * BB + b) * DHH + dir * HH + u] = hn;
        }
        p ^= 1;
        gsync(NBE);
    }
}

// ---------------- persistent decoder ----------------
#define SMEM_DEC ((1024 * 20 + 64 * 64) * 4)   // 96KB dynamic: Wsm + Asm
__global__ void __launch_bounds__(256, 1) dec_persist(int l0, int l1) {
    extern __shared__ __align__(16) float dyn[];
    float* Wsm = dyn;                                  // [1024*20]
    float (*Asm)[64] = (float(*)[64])(dyn + 1024 * 20);
    __shared__ float gsm[16][64];
    __shared__ __align__(16) float hd_s[DHH];
    __shared__ float sc[SS];
    __shared__ float red[128];
    int blk = blockIdx.x, tid = threadIdx.x;
    for (int i = tid; i < 16 * 1024; i += 256) {
        int r = i >> 10, k = i & 1023;
        Wsm[k * 20 + r] = g_Wcat[((size_t)blk * 16 + r) * 1024 + k];
    }
    __syncthreads();
    int q = tid >> 6, b = tid & 63;
    int kl = tid >> 4, b4 = (tid & 15) << 2;
    int uu = tid >> 6;
    for (int lvl = l0; lvl < l1; lvl++) {
        const float* pre = (lvl == 0) ? g_pre0 : g_pre1;
        float4 oh4 = *(const float4*)&g_ohcp[lvl * GD + blk * 16 + q * 4];
        for (int t = 0; t < SS; t++) {
            float a0 = 0.f, a1 = 0.f, a2 = 0.f, a3 = 0.f;
            // ---- phase A: hd half of the gate GEMM (Wsm k 512..1023) ----
            wres_gemm<8>(g_hdT, Wsm, 512, Asm, q, b, kl, b4, a0, a1, a2, a3);
            // blocks 0-63: attention for batch b = blk
            if (blk < 64) {
                int ab = blk;
                for (int i = tid; i < DHH; i += 256) hd_s[i] = g_hd[ab * DHH + i];
                __syncthreads();
                int warp = tid >> 5, lane = tid & 31;
                for (int s0 = warp; s0 < SS; s0 += 8) {
                    const float4* w4 = (const float4*)(g_wh + ((size_t)s0 * BB + ab) * DHH);
                    const float4* h4 = (const float4*)hd_s;
                    float sum = 0.f;
                    #pragma unroll
                    for (int qq = 0; qq < 4; qq++) {
                        float4 a = w4[lane * 4 + qq];
                        float4 c = h4[lane * 4 + qq];
                        sum += a.x * c.x + a.y * c.y + a.z * c.z + a.w * c.w;
                    }
                    #pragma unroll
                    for (int off = 16; off; off >>= 1) sum += __shfl_xor_sync(0xffffffffu, sum, off);
                    if (lane == 0) sc[s0] = sum;
                }
                __syncthreads();
                if (tid < 128) red[tid] = sc[tid];
                __syncthreads();
                for (int off = 64; off; off >>= 1) {
                    if (tid < off) red[tid] = fmaxf(red[tid], red[tid + off]);
                    __syncthreads();
                }
                float mx = red[0];
                __syncthreads();
                if (tid < 128) { float e = __expf(sc[tid] - mx); sc[tid] = e; red[tid] = e; }
                __syncthreads();
                for (int off = 64; off; off >>= 1) {
                    if (tid < off) red[tid] += red[tid + off];
                    __syncthreads();
                }
                float inv = 1.f / red[0];
                __syncthreads();
                for (int d = tid; d < DHH; d += 256) {
                    float acc = 0.f;
                    #pragma unroll 8
                    for (int s0 = 0; s0 < SS; s0++)
                        acc += sc[s0] * g_h[((size_t)s0 * BB + ab) * DHH + d];
                    g_ctxT[(size_t)d * BB + ab] = acc * inv;
                }
            }
            gsync(NBD);
            // ---- phase B: ctx half (Wsm k 0..511), then cell ----
            wres_gemm<8>(g_ctxT, Wsm, 0, Asm, q, b, kl, b4, a0, a1, a2, a3);
            float4 p4 = *(const float4*)&pre[((size_t)t * BB + b) * GD + blk * 16 + q * 4];
            gsm[q * 4 + 0][b] = a0 + p4.x + oh4.x;
            gsm[q * 4 + 1][b] = a1 + p4.y + oh4.y;
            gsm[q * 4 + 2][b] = a2 + p4.z + oh4.z;
            gsm[q * 4 + 3][b] = a3 + p4.w + oh4.w;
            __syncthreads();
            {
                float gi = gsm[0 + uu][b], gf = gsm[4 + uu][b], gg = gsm[8 + uu][b], go = gsm[12 + uu][b];
                int u = blk * 4 + uu;
                size_t ci = (size_t)u * BB + b;
                float c = g_cdT[ci];
                c = sigf(gf) * c + sigf(gi) * tanhf(gg);
                float hn = sigf(go) * tanhf(c);
                g_cdT[ci] = c;
                g_hdT[ci] = hn;
                g_hd[(size_t)b * DHH + u] = hn;
                g_dout[(((size_t)lvl * SS + t) * BB + b) * DHH + u] = hn;
            }
            gsync(NBD);
        }
    }
}

// ---------------- output projection ----------------
__global__ void out_proj(const float* __restrict__ W2, const float* __restrict__ b2,
                         float* __restrict__ out) {
    int m = blockIdx.x;
    int lane = threadIdx.x;
    const float* drow = g_dout + (size_t)m * DHH;
    float acc[CC] = {};
    for (int k = lane; k < DHH; k += 32) {
        float d = drow[k];
        #pragma unroll
        for (int c = 0; c < CC; c++) acc[c] += d * W2[c * DHH + k];
    }
    #pragma unroll
    for (int c = 0; c < CC; c++) {
        float v = acc[c];
        #pragma unroll
        for (int off = 16; off; off >>= 1) v += __shfl_xor_sync(0xffffffffu, v, off);
        if (lane == 0) out[(size_t)m * CC + c] = v + b2[c];
    }
}

// ---------------- host ----------------
static void* symaddr(const void* sym) { void* p = nullptr; cudaGetSymbolAddress(&p, sym); return p; }

extern "C" void kernel_launch(void* const* d_in, const int* in_sizes, int n_in,
                              void* d_out, int out_size) {
    const int*   seqs  = (const int*)d_in[0];
    const float* emb   = (const float*)d_in[2];
    const float* Wih_f = (const float*)d_in[3];
    const float* Whh_f = (const float*)d_in[4];
    const float* bih_f = (const float*)d_in[5];
    const float* bhh_f = (const float*)d_in[6];
    const float* Wih_b = (const float*)d_in[7];
    const float* Whh_b = (const float*)d_in[8];
    const float* bih_b = (const float*)d_in[9];
    const float* bhh_b = (const float*)d_in[10];
    const float* Wl    = (const float*)d_in[11];
    const float* Wih_d = (const float*)d_in[12];
    const float* Whh_d = (const float*)d_in[13];
    const float* bih_d = (const float*)d_in[14];
    const float* bhh_d = (const float*)d_in[15];
    const float* W2    = (const float*)d_in[16];
    const float* b2    = (const float*)d_in[17];
    float* out = (float*)d_out;

    float* px    = (float*)symaddr(g_x);
    float* pgxf  = (float*)symaddr(g_gxf);
    float* pgxb  = (float*)symaddr(g_gxb);
    float* ph    = (float*)symaddr(g_h);
    float* pwh   = (float*)symaddr(g_wh);
    float* ppreS = (float*)symaddr(g_preS);
    float* ppre0 = (float*)symaddr(g_pre0);
    float* ppre1 = (float*)symaddr(g_pre1);
    float* pdout = (float*)symaddr(g_dout);
    float* pWihp = (float*)symaddr(g_Wihp);
    float* pbep  = (float*)symaddr(g_bep);
    float* pWmid = (float*)symaddr(g_Wmid);
    float* pWprev= (float*)symaddr(g_Wprev);
    float* pbdp  = (float*)symaddr(g_bdp);

    cudaFuncSetAttribute(dec_persist, cudaFuncAttributeMaxDynamicSharedMemorySize, SMEM_DEC);

    // 0: prep
    k_prep<<<(PREP_TOTAL + 255) / 256, 256>>>(Whh_f, Whh_b, Wih_f, Wih_b,
                                              bih_f, bhh_f, bih_b, bhh_b,
                                              Wih_d, Whh_d, bih_d, bhh_d);
    // 1: embed
    k_embed<<<SS * BB, 128>>>(seqs, emb);
    // 2,3: encoder input GEMMs -> gx[t][b][n'] (permuted, bias folded)
    gemm_nt<<<dim3(SS * BB / 64, G4H / 64), 256>>>(px, EE, nullptr, pWihp, EE, pgxf, G4H, EE, nullptr, pbep);
    gemm_nt<<<dim3(SS * BB / 64, G4H / 64), 256>>>(px, EE, nullptr, pWihp + G4H * EE, EE, pgxb, G4H, EE, nullptr, pbep + G4H);
    // 4: encoder recurrence (W-resident persistent)
    enc_persist<<<NBE, 256>>>();
    // 5: preS = [h|x] @ Wmid^T + bd
    gemm_nt<<<dim3(SS * BB / 64, GD / 64), 256>>>(ph, DHH, px, pWmid, 1024, ppreS, GD, 1024, nullptr, pbdp);
    // 6: wh = h @ Wl^T
    gemm_nt<<<dim3(SS * BB / 64, DHH / 64), 256>>>(ph, DHH, nullptr, Wl, DHH, pwh, DHH, DHH, nullptr, nullptr);
    // 7: pre0 = preS + h @ Wprev^T
    gemm_nt<<<dim3(SS * BB / 64, GD / 64), 256>>>(ph, DHH, nullptr, pWprev, DHH, ppre0, GD, DHH, ppreS, nullptr);
    // 8: decoder level 0
    dec_persist<<<NBD, 256, SMEM_DEC>>>(0, 1);
    // 9: pre1 = preS + dout0 @ Wprev^T
    gemm_nt<<<dim3(SS * BB / 64, GD / 64), 256>>>(pdout, DHH, nullptr, pWprev, DHH, ppre1, GD, DHH, ppreS, nullptr);
    // 10: decoder levels 1-3
    dec_persist<<<NBD, 256, SMEM_DEC>>>(1, 4);
    // 11: logits
    out_proj<<<LMAXX * SS * BB, 32>>>(W2, b2, out);
}

// round 10
// speedup vs baseline: 2.3128x; 1.0001x over previous
#include <cuda_runtime.h>
#include <math.h>

// ---------------- problem dims ----------------
#define SS    128
#define BB    64
#define EE    512
#define HH    256
#define DHH   512
#define G4H   1024
#define GD    2048
#define LDWD  2052
#define LMAXX 4
#define CC    9

#define NBE   128
#define NBD   128

// gate-locality permutations: each block owns all 4 gates of 4 hidden units.
// encoder: n' = ublk*16 + q*4 + uu  ->  n = q*256 + ublk*4 + uu   (ublk 0..63)
__device__ __forceinline__ int enperm(int np) { return (((np >> 2) & 3) << 8) + ((np >> 4) << 2) + (np & 3); }
// decoder: n' = blk*16 + q*4 + uu   ->  n = q*512 + blk*4 + uu    (blk 0..127)
__device__ __forceinline__ int deperm(int np) { return (((np >> 2) & 3) << 9) + ((np >> 4) << 2) + (np & 3); }

// ---------------- static device scratch ----------------
__device__ float g_x   [SS*BB*EE];
__device__ float g_gxf [SS*BB*G4H];      // [t][b][n'] permuted
__device__ float g_gxb [SS*BB*G4H];
__device__ float g_h   [SS*BB*DHH];
__device__ float g_wh  [SS*BB*DHH];
__device__ float g_preS[SS*BB*GD];       // [t][b][n'] permuted
__device__ float g_pre0[SS*BB*GD];
__device__ float g_pre1[SS*BB*GD];
__device__ float g_dout[LMAXX*SS*BB*DHH];
__device__ float g_hencT[2*2*HH*BB];     // [p][dir][u][b] k-major encoder h
__device__ float g_cencT[2*HH*BB];       // [dir][u][b]
__device__ float g_hd  [BB*DHH];         // [b][u]  (attention)
__device__ float g_hdT [DHH*BB];         // [u][b]  (GEMM staging)
__device__ float g_cdT [DHH*BB];
__device__ float g_ctxT[DHH*BB];         // [d][b]
__device__ float g_Whhp[2*G4H*HH];       // permuted rows [dir][n'][k]
__device__ float g_Wihp[2*G4H*EE];
__device__ float g_bep [2*G4H];
__device__ float g_Wcat[GD*1024];        // permuted rows: [Wih_d[:, :512] | Whh_d]
__device__ float g_Wmid[GD*1024];        // permuted rows: Wih_d[:, 512:1536]
__device__ float g_Wprev[GD*DHH];        // permuted rows: Wih_d[:, 1536:2048]
__device__ float g_bdp [GD];
__device__ float g_ohcp[LMAXX*GD];

__device__ unsigned g_barCount;
__device__ volatile unsigned g_barGen;

__device__ __forceinline__ float sigf(float x) { return 1.0f / (1.0f + __expf(-x)); }

__device__ __forceinline__ void gsync(unsigned nb) {
    __syncthreads();
    if (threadIdx.x == 0) {
        unsigned gen = g_barGen;
        __threadfence();
        if (atomicAdd(&g_barCount, 1) == nb - 1) {
            g_barCount = 0;
            __threadfence();
            g_barGen = gen + 1;
        } else {
            while (g_barGen == gen) {}
            __threadfence();
        }
    }
    __syncthreads();
}

// ---------------- prep: permute weights, fold biases, zero states ----------------
#define Z_TOTAL 196608
#define PREP_TOTAL (Z_TOTAL + 524288 + 1048576 + 2048 + 2097152 + 2097152 + 1048576 + 2048 + 8192)
__global__ void k_prep(const float* __restrict__ Whh_f, const float* __restrict__ Whh_b,
                       const float* __restrict__ Wih_f, const float* __restrict__ Wih_b,
                       const float* __restrict__ bih_f, const float* __restrict__ bhh_f,
                       const float* __restrict__ bih_b, const float* __restrict__ bhh_b,
                       const float* __restrict__ Wih_d, const float* __restrict__ Whh_d,
                       const float* __restrict__ bih_d, const float* __restrict__ bhh_d) {
    long long i = (long long)blockIdx.x * 256 + threadIdx.x;
    if (i < Z_TOTAL) {
        if (i < 65536) g_hencT[i] = 0.f;
        else if (i < 98304) g_cencT[i - 65536] = 0.f;
        else if (i < 131072) g_hd[i - 98304] = 0.f;
        else if (i < 163840) g_hdT[i - 131072] = 0.f;
        else g_cdT[i - 163840] = 0.f;
        return;
    }
    i -= Z_TOTAL;
    if (i < 524288) { // Whhp
        int dir = (int)(i >> 18), r = (int)(i & 262143);
        int np = r >> 8, k = r & 255;
        int n = enperm(np);
        g_Whhp[i] = (dir ? Whh_b : Whh_f)[n * HH + k];
        return;
    }
    i -= 524288;
    if (i < 1048576) { // Wihp
        int dir = (int)(i >> 19), r = (int)(i & 524287);
        int np = r >> 9, k = r & 511;
        int n = enperm(np);
        g_Wihp[i] = (dir ? Wih_b : Wih_f)[n * EE + k];
        return;
    }
    i -= 1048576;
    if (i < 2048) { // encoder bias
        int dir = (int)(i >> 10), np = (int)(i & 1023);
        int n = enperm(np);
        g_bep[i] = dir ? (bih_b[n] + bhh_b[n]) : (bih_f[n] + bhh_f[n]);
        return;
    }
    i -= 2048;
    if (i < 2097152) { // Wcat
        int np = (int)(i >> 10), k = (int)(i & 1023);
        int n = deperm(np);
        g_Wcat[i] = (k < 512) ? Wih_d[(size_t)n * LDWD + k] : Whh_d[(size_t)n * DHH + (k - 512)];
        return;
    }
    i -= 2097152;
    if (i < 2097152) { // Wmid
        int np = (int)(i >> 10), k = (int)(i & 1023);
        int n = deperm(np);
        g_Wmid[i] = Wih_d[(size_t)n * LDWD + 512 + k];
        return;
    }
    i -= 2097152;
    if (i < 1048576) { // Wprev
        int np = (int)(i >> 9), k = (int)(i & 511);
        int n = deperm(np);
        g_Wprev[i] = Wih_d[(size_t)n * LDWD + 1536 + k];
        return;
    }
    i -= 1048576;
    if (i < 2048) { // decoder bias
        int n = deperm((int)i);
        g_bdp[i] = bih_d[n] + bhh_d[n];
        return;
    }
    i -= 2048;
    if (i < 8192) { // one-hot columns
        int lvl = (int)(i >> 11), np = (int)(i & 2047);
        int n = deperm(np);
        g_ohcp[i] = Wih_d[(size_t)n * LDWD + GD + lvl];
        return;
    }
}

__global__ void k_embed(const int* __restrict__ seqs, const float* __restrict__ emb) {
    int m = blockIdx.x;            // m = s*64 + b
    int s0 = m >> 6, b = m & 63;
    int row = seqs[b * SS + s0];
    const float4* src = (const float4*)(emb + (size_t)row * EE);
    float4* dst = (float4*)(g_x + (size_t)m * EE);
    dst[threadIdx.x] = src[threadIdx.x];
}

// ---------------- precompute GEMM (conflict-free, measured ~30TF/s) ----------------
__global__ void __launch_bounds__(256) gemm_nt(const float* __restrict__ A, int lda,
                        const float* __restrict__ A2,
                        const float* __restrict__ W, int ldw,
                        float* __restrict__ C, int N, int K,
                        const float* __restrict__ add, const float* __restrict__ bias) {
    __shared__ __align__(16) float As[16][68];
    __shared__ __align__(16) float Ws[16][68];
    int m0 = blockIdx.x * 64, n0 = blockIdx.y * 64;
    int tid = threadIdx.x;
    int tm = (tid >> 4) << 2, tn = (tid & 15) << 2;
    float acc[4][4] = {};
    for (int k0 = 0; k0 < K; k0 += 16) {
        const float* Asrc = A;
        int kk0 = k0;
        if (A2 && k0 >= 512) { Asrc = A2; kk0 = k0 - 512; }
        #pragma unroll
        for (int i = tid; i < 1024; i += 256) {
            int r = i >> 4, k = i & 15;
            As[k][r] = Asrc[(size_t)(m0 + r) * lda + kk0 + k];
            Ws[k][r] = W[(size_t)(n0 + r) * ldw + k0 + k];
        }
        __syncthreads();
        #pragma unroll
        for (int k = 0; k < 16; k++) {
            float4 a4 = *(const float4*)&As[k][tm];
            float4 w4 = *(const float4*)&Ws[k][tn];
            acc[0][0] += a4.x * w4.x; acc[0][1] += a4.x * w4.y; acc[0][2] += a4.x * w4.z; acc[0][3] += a4.x * w4.w;
            acc[1][0] += a4.y * w4.x; acc[1][1] += a4.y * w4.y; acc[1][2] += a4.y * w4.z; acc[1][3] += a4.y * w4.w;
            acc[2][0] += a4.z * w4.x; acc[2][1] += a4.z * w4.y; acc[2][2] += a4.z * w4.z; acc[2][3] += a4.z * w4.w;
            acc[3][0] += a4.w * w4.x; acc[3][1] += a4.w * w4.y; acc[3][2] += a4.w * w4.z; acc[3][3] += a4.w * w4.w;
        }
        __syncthreads();
    }
    #pragma unroll
    for (int i = 0; i < 4; i++)
        #pragma unroll
        for (int j = 0; j < 4; j++) {
            size_t m = m0 + tm + i, n = n0 + tn + j;
            float v = acc[i][j];
            if (add)  v += add[m * N + n];
            if (bias) v += bias[n];
            C[m * N + n] = v;
        }
}

// ---------------- W-resident GEMM half: acc += AT-slice @ Wsm-slice ----------------
// AT: [Kh=chunks*64][64] k-major activations; Wsm: [k][20] (row r at +r, float4 at q*4)
template<int CHUNKS>
__device__ __forceinline__ void wres_gemm(const float* __restrict__ AT,
                                          const float* __restrict__ Wsm, int kbase,
                                          float (*Asm)[64],
                                          int q, int b, int kl, int b4,
                                          float& a0, float& a1, float& a2, float& a3) {
    float4 pf0 = *(const float4*)&AT[(size_t)(kl     ) * 64 + b4];
    float4 pf1 = *(const float4*)&AT[(size_t)(kl + 16) * 64 + b4];
    float4 pf2 = *(const float4*)&AT[(size_t)(kl + 32) * 64 + b4];
    float4 pf3 = *(const float4*)&AT[(size_t)(kl + 48) * 64 + b4];
    for (int c = 0; c < CHUNKS; c++) {
        __syncthreads();
        *(float4*)&Asm[kl     ][b4] = pf0;
        *(float4*)&Asm[kl + 16][b4] = pf1;
        *(float4*)&Asm[kl + 32][b4] = pf2;
        *(float4*)&Asm[kl + 48][b4] = pf3;
        __syncthreads();
        if (c < CHUNKS - 1) {
            const float* src = AT + (size_t)(c + 1) * 64 * 64;
            pf0 = *(const float4*)&src[(size_t)(kl     ) * 64 + b4];
            pf1 = *(const float4*)&src[(size_t)(kl + 16) * 64 + b4];
            pf2 = *(const float4*)&src[(size_t)(kl + 32) * 64 + b4];
            pf3 = *(const float4*)&src[(size_t)(kl + 48) * 64 + b4];
        }
        const float* wp = Wsm + (size_t)(kbase + c * 64) * 20 + q * 4;
        #pragma unroll 16
        for (int k = 0; k < 64; k++) {
            float a = Asm[k][b];
            float4 w = *(const float4*)&wp[k * 20];
            a0 += a * w.x; a1 += a * w.y; a2 += a * w.z; a3 += a * w.w;
        }
    }
}

// ---------------- persistent encoder ----------------
__global__ void __launch_bounds__(256, 1) enc_persist() {
    __shared__ __align__(16) float Wsm[HH * 20];     // 20KB
    __shared__ __align__(16) float Asm[64][64];      // 16KB
    __shared__ float gsm[16][64];                    // 4KB
    int blk = blockIdx.x, tid = threadIdx.x;
    int dir = blk >> 6, ub = blk & 63;
    for (int i = tid; i < 16 * HH; i += 256) {
        int r = i >> 8, k = i & 255;
        Wsm[k * 20 + r] = g_Whhp[((size_t)dir * G4H + ub * 16 + r) * HH + k];
    }
    __syncthreads();
    int q = tid >> 6, b = tid & 63;
    int kl = tid >> 4, b4 = (tid & 15) << 2;
    int uu = tid >> 6;
    int p = 0;
    for (int t = 0; t < SS; t++) {
        const float* AT = g_hencT + ((size_t)p * 2 + dir) * HH * BB;
        float a0 = 0.f, a1 = 0.f, a2 = 0.f, a3 = 0.f;
        wres_gemm<4>(AT, Wsm, 0, Asm, q, b, kl, b4, a0, a1, a2, a3);
        int s0 = dir ? (SS - 1 - t) : t;
        float4 g4 = *(const float4*)((dir ? g_gxb : g_gxf) + ((size_t)s0 * BB + b) * G4H + ub * 16 + q * 4);
        gsm[q * 4 + 0][b] = a0 + g4.x;
        gsm[q * 4 + 1][b] = a1 + g4.y;
        gsm[q * 4 + 2][b] = a2 + g4.z;
        gsm[q * 4 + 3][b] = a3 + g4.w;
        __syncthreads();
        {
            float gi = gsm[0 + uu][b], gf = gsm[4 + uu][b], gg = gsm[8 + uu][b], go = gsm[12 + uu][b];
            int u = ub * 4 + uu;
            size_t ci = ((size_t)dir * HH + u) * BB + b;
            float c = g_cencT[ci];
            c = sigf(gf) * c + sigf(gi) * tanhf(gg);
            float hn = sigf(go) * tanhf(c);
            g_cencT[ci] = c;
            g_hencT[((size_t)(p ^ 1) * 2 + dir) * HH * BB + (size_t)u * BB + b] = hn;
            g_h[((size_t)s0 * BB + b) * DHH + dir * HH + u] = hn;
        }
        p ^= 1;
        gsync(NBE);
    }
}

// ---------------- persistent decoder ----------------
#define SMEM_DEC ((1024 * 20 + 64 * 64) * 4)   // 96KB dynamic: Wsm + Asm
__global__ void __launch_bounds__(256, 1) dec_persist(int l0, int l1) {
    extern __shared__ __align__(16) float dyn[];
    float* Wsm = dyn;                                  // [1024*20]
    float (*Asm)[64] = (float(*)[64])(dyn + 1024 * 20);
    __shared__ float gsm[16][64];
    __shared__ __align__(16) float hd_s[DHH];
    __shared__ float sc[SS];
    __shared__ float red[128];
    int blk = blockIdx.x, tid = threadIdx.x;
    for (int i = tid; i < 16 * 1024; i += 256) {
        int r = i >> 10, k = i & 1023;
        Wsm[k * 20 + r] = g_Wcat[((size_t)blk * 16 + r) * 1024 + k];
    }
    __syncthreads();
    int q = tid >> 6, b = tid & 63;
    int kl = tid >> 4, b4 = (tid & 15) << 2;
    int uu = tid >> 6;
    for (int lvl = l0; lvl < l1; lvl++) {
        const float* pre = (lvl == 0) ? g_pre0 : g_pre1;
        float4 oh4 = *(const float4*)&g_ohcp[lvl * GD + blk * 16 + q * 4];
        for (int t = 0; t < SS; t++) {
            float a0 = 0.f, a1 = 0.f, a2 = 0.f, a3 = 0.f;
            // ---- phase A: hd half of the gate GEMM (Wsm k 512..1023) ----
            wres_gemm<8>(g_hdT, Wsm, 512, Asm, q, b, kl, b4, a0, a1, a2, a3);
            // blocks 0-63: attention for batch b = blk
            if (blk < 64) {
                int ab = blk;
                for (int i = tid; i < DHH; i += 256) hd_s[i] = g_hd[ab * DHH + i];
                __syncthreads();
                int warp = tid >> 5, lane = tid & 31;
                for (int s0 = warp; s0 < SS; s0 += 8) {
                    const float4* w4 = (const float4*)(g_wh + ((size_t)s0 * BB + ab) * DHH);
                    const float4* h4 = (const float4*)hd_s;
                    float sum = 0.f;
                    #pragma unroll
                    for (int qq = 0; qq < 4; qq++) {
                        float4 a = w4[lane * 4 + qq];
                        float4 c = h4[lane * 4 + qq];
                        sum += a.x * c.x + a.y * c.y + a.z * c.z + a.w * c.w;
                    }
                    #pragma unroll
                    for (int off = 16; off; off >>= 1) sum += __shfl_xor_sync(0xffffffffu, sum, off);
                    if (lane == 0) sc[s0] = sum;
                }
                __syncthreads();
                if (tid < 128) red[tid] = sc[tid];
                __syncthreads();
                for (int off = 64; off; off >>= 1) {
                    if (tid < off) red[tid] = fmaxf(red[tid], red[tid + off]);
                    __syncthreads();
                }
                float mx = red[0];
                __syncthreads();
                if (tid < 128) { float e = __expf(sc[tid] - mx); sc[tid] = e; red[tid] = e; }
                __syncthreads();
                for (int off = 64; off; off >>= 1) {
                    if (tid < off) red[tid] += red[tid + off];
                    __syncthreads();
                }
                float inv = 1.f / red[0];
                __syncthreads();
                for (int d = tid; d < DHH; d += 256) {
                    float acc = 0.f;
                    #pragma unroll 8
                    for (int s0 = 0; s0 < SS; s0++)
                        acc += sc[s0] * g_h[((size_t)s0 * BB + ab) * DHH + d];
                    g_ctxT[(size_t)d * BB + ab] = acc * inv;
                }
            }
            gsync(NBD);
            // ---- phase B: ctx half (Wsm k 0..511), then cell ----
            wres_gemm<8>(g_ctxT, Wsm, 0, Asm, q, b, kl, b4, a0, a1, a2, a3);
            float4 p4 = *(const float4*)&pre[((size_t)t * BB + b) * GD + blk * 16 + q * 4];
            gsm[q * 4 + 0][b] = a0 + p4.x + oh4.x;
            gsm[q * 4 + 1][b] = a1 + p4.y + oh4.y;
            gsm[q * 4 + 2][b] = a2 + p4.z + oh4.z;
            gsm[q * 4 + 3][b] = a3 + p4.w + oh4.w;
            __syncthreads();
            {
                float gi = gsm[0 + uu][b], gf = gsm[4 + uu][b], gg = gsm[8 + uu][b], go = gsm[12 + uu][b];
                int u = blk * 4 + uu;
                size_t ci = (size_t)u * BB + b;
                float c = g_cdT[ci];
                c = sigf(gf) * c + sigf(gi) * tanhf(gg);
                float hn = sigf(go) * tanhf(c);
                g_cdT[ci] = c;
                g_hdT[ci] = hn;
                g_hd[(size_t)b * DHH + u] = hn;
                g_dout[(((size_t)lvl * SS + t) * BB + b) * DHH + u] = hn;
            }
            gsync(NBD);
        }
    }
}

// ---------------- output projection ----------------
__global__ void out_proj(const float* __restrict__ W2, const float* __restrict__ b2,
                         float* __restrict__ out) {
    int m = blockIdx.x;
    int lane = threadIdx.x;
    const float* drow = g_dout + (size_t)m * DHH;
    float acc[CC] = {};
    for (int k = lane; k < DHH; k += 32) {
        float d = drow[k];
        #pragma unroll
        for (int c = 0; c < CC; c++) acc[c] += d * W2[c * DHH + k];
    }
    #pragma unroll
    for (int c = 0; c < CC; c++) {
        float v = acc[c];
        #pragma unroll
        for (int off = 16; off; off >>= 1) v += __shfl_xor_sync(0xffffffffu, v, off);
        if (lane == 0) out[(size_t)m * CC + c] = v + b2[c];
    }
}

// ---------------- host ----------------
static void* symaddr(const void* sym) { void* p = nullptr; cudaGetSymbolAddress(&p, sym); return p; }

extern "C" void kernel_launch(void* const* d_in, const int* in_sizes, int n_in,
                              void* d_out, int out_size) {
    const int*   seqs  = (const int*)d_in[0];
    const float* emb   = (const float*)d_in[2];
    const float* Wih_f = (const float*)d_in[3];
    const float* Whh_f = (const float*)d_in[4];
    const float* bih_f = (const float*)d_in[5];
    const float* bhh_f = (const float*)d_in[6];
    const float* Wih_b = (const float*)d_in[7];
    const float* Whh_b = (const float*)d_in[8];
    const float* bih_b = (const float*)d_in[9];
    const float* bhh_b = (const float*)d_in[10];
    const float* Wl    = (const float*)d_in[11];
    const float* Wih_d = (const float*)d_in[12];
    const float* Whh_d = (const float*)d_in[13];
    const float* bih_d = (const float*)d_in[14];
    const float* bhh_d = (const float*)d_in[15];
    const float* W2    = (const float*)d_in[16];
    const float* b2    = (const float*)d_in[17];
    float* out = (float*)d_out;

    float* px    = (float*)symaddr(g_x);
    float* pgxf  = (float*)symaddr(g_gxf);
    float* pgxb  = (float*)symaddr(g_gxb);
    float* ph    = (float*)symaddr(g_h);
    float* pwh   = (float*)symaddr(g_wh);
    float* ppreS = (float*)symaddr(g_preS);
    float* ppre0 = (float*)symaddr(g_pre0);
    float* ppre1 = (float*)symaddr(g_pre1);
    float* pdout = (float*)symaddr(g_dout);
    float* pWihp = (float*)symaddr(g_Wihp);
    float* pbep  = (float*)symaddr(g_bep);
    float* pWmid = (float*)symaddr(g_Wmid);
    float* pWprev= (float*)symaddr(g_Wprev);
    float* pbdp  = (float*)symaddr(g_bdp);

    cudaFuncSetAttribute(dec_persist, cudaFuncAttributeMaxDynamicSharedMemorySize, SMEM_DEC);

    // 0: prep
    k_prep<<<(PREP_TOTAL + 255) / 256, 256>>>(Whh_f, Whh_b, Wih_f, Wih_b,
                                              bih_f, bhh_f, bih_b, bhh_b,
                                              Wih_d, Whh_d, bih_d, bhh_d);
    // 1: embed
    k_embed<<<SS * BB, 128>>>(seqs, emb);
    // 2,3: encoder input GEMMs -> gx[t][b][n'] (permuted, bias folded)
    gemm_nt<<<dim3(SS * BB / 64, G4H / 64), 256>>>(px, EE, nullptr, pWihp, EE, pgxf, G4H, EE, nullptr, pbep);
    gemm_nt<<<dim3(SS * BB / 64, G4H / 64), 256>>>(px, EE, nullptr, pWihp + G4H * EE, EE, pgxb, G4H, EE, nullptr, pbep + G4H);
    // 4: encoder recurrence (W-resident persistent)
    enc_persist<<<NBE, 256>>>();
    // 5: preS = [h|x] @ Wmid^T + bd
    gemm_nt<<<dim3(SS * BB / 64, GD / 64), 256>>>(ph, DHH, px, pWmid, 1024, ppreS, GD, 1024, nullptr, pbdp);
    // 6: wh = h @ Wl^T
    gemm_nt<<<dim3(SS * BB / 64, DHH / 64), 256>>>(ph, DHH, nullptr, Wl, DHH, pwh, DHH, DHH, nullptr, nullptr);
    // 7: pre0 = preS + h @ Wprev^T
    gemm_nt<<<dim3(SS * BB / 64, GD / 64), 256>>>(ph, DHH, nullptr, pWprev, DHH, ppre0, GD, DHH, ppreS, nullptr);
    // 8: decoder level 0
    dec_persist<<<NBD, 256, SMEM_DEC>>>(0, 1);
    // 9: pre1 = preS + dout0 @ Wprev^T
    gemm_nt<<<dim3(SS * BB / 64, GD / 64), 256>>>(pdout, DHH, nullptr, pWprev, DHH, ppre1, GD, DHH, ppreS, nullptr);
    // 10: decoder levels 1-3
    dec_persist<<<NBD, 256, SMEM_DEC>>>(1, 4);
    // 11: logits
    out_proj<<<LMAXX * SS * BB, 32>>>(W2, b2, out);
}

// round 11
// speedup vs baseline: 2.3261x; 1.0058x over previous
#include <cuda_runtime.h>
#include <math.h>

// ---------------- problem dims ----------------
#define SS    128
#define BB    64
#define EE    512
#define HH    256
#define DHH   512
#define G4H   1024
#define GD    2048
#define LDWD  2052
#define LMAXX 4
#define CC    9

#define NBE   128
#define NBD   128

typedef unsigned long long ull;

// gate-locality permutations (unchanged from R10): block owns all 4 gates of 4 units
__device__ __forceinline__ int enperm(int np) { return (((np >> 2) & 3) << 8) + ((np >> 4) << 2) + (np & 3); }
__device__ __forceinline__ int deperm(int np) { return (((np >> 2) & 3) << 9) + ((np >> 4) << 2) + (np & 3); }

// ---------------- static device scratch ----------------
__device__ float g_x   [SS*BB*EE];
__device__ float g_gxf [SS*BB*G4H];      // TRANSPOSED: [s][np][b]
__device__ float g_gxb [SS*BB*G4H];      // TRANSPOSED: [s][np][b]
__device__ float g_h   [SS*BB*DHH];      // [s][b][d] row-major
__device__ float g_wh  [SS*BB*DHH];      // [s][b][d] row-major
__device__ float g_pre0[SS*BB*GD];       // TRANSPOSED: [t][np][b]
__device__ float g_pre1[SS*BB*GD];       // TRANSPOSED: [t][np][b]
__device__ float g_dout[LMAXX*SS*BB*DHH];// [lvl][t][b][u]
__device__ float g_hencT[2*2*HH*BB];     // [p][dir][u][b]
__device__ float g_cencT[2*HH*BB];
__device__ float g_hd  [BB*DHH];         // [b][u] (attention reads)
__device__ float g_hdT [DHH*BB];         // [u][b] (GEMM k-major)
__device__ float g_cdT [DHH*BB];
__device__ float g_ctxP[2*DHH*BB];       // [half][d][b] unnormalized partial ctx
__device__ float g_attM[2*BB];           // [b*2+half] local max
__device__ float g_attS[2*BB];           // [b*2+half] local sum
__device__ float g_Whhp[2*G4H*HH];       // permuted rows [dir][np][k]
__device__ float g_Wihp[2*G4H*EE];
__device__ float g_bep [2*G4H];
__device__ float g_Wcat[GD*1024];        // permuted rows: [Wih_d[:, :512] | Whh_d]
__device__ float g_Wmid0[GD*1024];       // permuted rows: Wih_d[:,512:1536] with h-cols += Wprev
__device__ float g_Wprev[GD*DHH];        // permuted rows: Wih_d[:, 1536:2048]
__device__ float g_bdp [GD];
__device__ float g_ohcp[LMAXX*GD];

__device__ unsigned g_barCount;
__device__ volatile unsigned g_barGen;

__device__ __forceinline__ float sigf(float x) { return 1.0f / (1.0f + __expf(-x)); }

__device__ __forceinline__ void gsync(unsigned nb) {
    __syncthreads();
    if (threadIdx.x == 0) {
        unsigned gen = g_barGen;
        __threadfence();
        if (atomicAdd(&g_barCount, 1) == nb - 1) {
            g_barCount = 0;
            __threadfence();
            g_barGen = gen + 1;
        } else {
            while (g_barGen == gen) {}
            __threadfence();
        }
    }
    __syncthreads();
}

// packed f32x2 FMA (SASS FFMA2: 2 MACs/instr on the rt-2 fma pipe)
__device__ __forceinline__ ull fma2(ull a, ull b, ull c) {
    ull d;
    asm("fma.rn.f32x2 %0, %1, %2, %3;" : "=l"(d) : "l"(a), "l"(b), "l"(c));
    return d;
}
__device__ __forceinline__ float2 unpack2(ull v) {
    float2 r;
    asm("mov.b64 {%0, %1}, %2;" : "=f"(r.x), "=f"(r.y) : "l"(v));
    return r;
}

// ---------------- prep ----------------
#define Z_TOTAL 196608
#define PREP_TOTAL (Z_TOTAL + 524288 + 1048576 + 2048 + 2097152 + 2097152 + 1048576 + 2048 + 8192)
__global__ void k_prep(const float* __restrict__ Whh_f, const float* __restrict__ Whh_b,
                       const float* __restrict__ Wih_f, const float* __restrict__ Wih_b,
                       const float* __restrict__ bih_f, const float* __restrict__ bhh_f,
                       const float* __restrict__ bih_b, const float* __restrict__ bhh_b,
                       const float* __restrict__ Wih_d, const float* __restrict__ Whh_d,
                       const float* __restrict__ bih_d, const float* __restrict__ bhh_d) {
    long long i = (long long)blockIdx.x * 256 + threadIdx.x;
    if (i < Z_TOTAL) {
        if (i < 65536) g_hencT[i] = 0.f;
        else if (i < 98304) g_cencT[i - 65536] = 0.f;
        else if (i < 131072) g_hd[i - 98304] = 0.f;
        else if (i < 163840) g_hdT[i - 131072] = 0.f;
        else g_cdT[i - 163840] = 0.f;
        return;
    }
    i -= Z_TOTAL;
    if (i < 524288) { // Whhp
        int dir = (int)(i >> 18), r = (int)(i & 262143);
        int np = r >> 8, k = r & 255;
        int n = enperm(np);
        g_Whhp[i] = (dir ? Whh_b : Whh_f)[n * HH + k];
        return;
    }
    i -= 524288;
    if (i < 1048576) { // Wihp
        int dir = (int)(i >> 19), r = (int)(i & 524287);
        int np = r >> 9, k = r & 511;
        int n = enperm(np);
        g_Wihp[i] = (dir ? Wih_b : Wih_f)[n * EE + k];
        return;
    }
    i -= 1048576;
    if (i < 2048) { // encoder bias
        int dir = (int)(i >> 10), np = (int)(i & 1023);
        int n = enperm(np);
        g_bep[i] = dir ? (bih_b[n] + bhh_b[n]) : (bih_f[n] + bhh_f[n]);
        return;
    }
    i -= 2048;
    if (i < 2097152) { // Wcat
        int np = (int)(i >> 10), k = (int)(i & 1023);
        int n = deperm(np);
        g_Wcat[i] = (k < 512) ? Wih_d[(size_t)n * LDWD + k] : Whh_d[(size_t)n * DHH + (k - 512)];
        return;
    }
    i -= 2097152;
    if (i < 2097152) { // Wmid0 = Wih_d[:,512:1536] with first 512 k-cols += Wprev
        int np = (int)(i >> 10), k = (int)(i & 1023);
        int n = deperm(np);
        float v = Wih_d[(size_t)n * LDWD + 512 + k];
        if (k < 512) v += Wih_d[(size_t)n * LDWD + 1536 + k];
        g_Wmid0[i] = v;
        return;
    }
    i -= 2097152;
    if (i < 1048576) { // Wprev
        int np = (int)(i >> 9), k = (int)(i & 511);
        int n = deperm(np);
        g_Wprev[i] = Wih_d[(size_t)n * LDWD + 1536 + k];
        return;
    }
    i -= 1048576;
    if (i < 2048) { // decoder bias
        int n = deperm((int)i);
        g_bdp[i] = bih_d[n] + bhh_d[n];
        return;
    }
    i -= 2048;
    if (i < 8192) { // one-hot columns
        int lvl = (int)(i >> 11), np = (int)(i & 2047);
        int n = deperm(np);
        g_ohcp[i] = Wih_d[(size_t)n * LDWD + GD + lvl];
        return;
    }
}

__global__ void k_embed(const int* __restrict__ seqs, const float* __restrict__ emb) {
    int m = blockIdx.x;            // m = s*64 + b
    int s0 = m >> 6, b = m & 63;
    int row = seqs[b * SS + s0];
    const float4* src = (const float4*)(emb + (size_t)row * EE);
    float4* dst = (float4*)(g_x + (size_t)m * EE);
    dst[threadIdx.x] = src[threadIdx.x];
}

// ---------------- precompute GEMM core (64x64 tiles, ~31 TF/s measured) ----------------
// C = (A - Asub)[M,K] * W[N,K]^T (+add)(+bias). A2 = source for k>=512 (concat).
// tpose: C/add indexed as [(m>>6)*N + n]*64 + (m&63)  (i.e. [t][n][b]).
__device__ __forceinline__ void gemm_core(const float* __restrict__ A, int lda,
                        const float* __restrict__ A2, const float* __restrict__ Asub,
                        const float* __restrict__ W, int ldw,
                        float* __restrict__ C, int N, int K,
                        const float* __restrict__ add, const float* __restrict__ bias,
                        int tpose, int m0, int n0) {
    __shared__ __align__(16) float As[16][68];
    __shared__ __align__(16) float Ws[16][68];
    int tid = threadIdx.x;
    int tm = (tid >> 4) << 2, tn = (tid & 15) << 2;
    float acc[4][4] = {};
    for (int k0 = 0; k0 < K; k0 += 16) {
        const float* Asrc = A;
        int kk0 = k0;
        bool second = (A2 && k0 >= 512);
        if (second) { Asrc = A2; kk0 = k0 - 512; }
        #pragma unroll
        for (int i = tid; i < 1024; i += 256) {
            int r = i >> 4, k = i & 15;
            float v = Asrc[(size_t)(m0 + r) * lda + kk0 + k];
            if (Asub && !second) v -= Asub[(size_t)(m0 + r) * lda + kk0 + k];
            As[k][r] = v;
            Ws[k][r] = W[(size_t)(n0 + r) * ldw + k0 + k];
        }
        __syncthreads();
        #pragma unroll
        for (int k = 0; k < 16; k++) {
            float4 a4 = *(const float4*)&As[k][tm];
            float4 w4 = *(const float4*)&Ws[k][tn];
            acc[0][0] += a4.x * w4.x; acc[0][1] += a4.x * w4.y; acc[0][2] += a4.x * w4.z; acc[0][3] += a4.x * w4.w;
            acc[1][0] += a4.y * w4.x; acc[1][1] += a4.y * w4.y; acc[1][2] += a4.y * w4.z; acc[1][3] += a4.y * w4.w;
            acc[2][0] += a4.z * w4.x; acc[2][1] += a4.z * w4.y; acc[2][2] += a4.z * w4.z; acc[2][3] += a4.z * w4.w;
            acc[3][0] += a4.w * w4.x; acc[3][1] += a4.w * w4.y; acc[3][2] += a4.w * w4.z; acc[3][3] += a4.w * w4.w;
        }
        __syncthreads();
    }
    #pragma unroll
    for (int i = 0; i < 4; i++)
        #pragma unroll
        for (int j = 0; j < 4; j++) {
            int m = m0 + tm + i, n = n0 + tn + j;
            float v = acc[i][j];
            if (bias) v += bias[n];
            if (tpose) {
                size_t idx = ((size_t)(m >> 6) * N + n) * 64 + (m & 63);
                if (add) v += add[idx];
                C[idx] = v;
            } else {
                size_t idx = (size_t)m * N + n;
                if (add) v += add[idx];
                C[idx] = v;
            }
        }
}

// encoder input GEMMs, both dirs (grid 128,16,2) -> transposed gx
__global__ void __launch_bounds__(256) k_encg() {
    int z = blockIdx.z;
    gemm_core(g_x, EE, nullptr, nullptr,
              g_Wihp + (size_t)z * G4H * EE, EE,
              z ? g_gxb : g_gxf, G4H, EE,
              nullptr, g_bep + z * G4H, 1,
              blockIdx.x * 64, blockIdx.y * 64);
}

// pre0 = [h|x]@Wmid0 + bd (transposed)  AND  wh = h@Wl (row-major). grid (128, 40)
__global__ void __launch_bounds__(256) k_pre(const float* __restrict__ Wl) {
    if (blockIdx.y < 32) {
        gemm_core(g_h, DHH, g_x, nullptr, g_Wmid0, 1024, g_pre0, GD, 1024,
                  nullptr, g_bdp, 1, blockIdx.x * 64, blockIdx.y * 64);
    } else {
        gemm_core(g_h, DHH, nullptr, nullptr, Wl, DHH, g_wh, DHH, DHH,
                  nullptr, nullptr, 0, blockIdx.x * 64, (blockIdx.y - 32) * 64);
    }
}

// pre1 = pre0 + (dout0 - h)@Wprev  (transposed). grid (128, 32)
__global__ void __launch_bounds__(256) k_pre1() {
    gemm_core(g_dout, DHH, nullptr, g_h, g_Wprev, DHH, g_pre1, GD, DHH,
              g_pre0, nullptr, 1, blockIdx.x * 64, blockIdx.y * 64);
}

// ---------------- W-resident f32x2 GEMM half ----------------
// AT: [K][64] k-major; wp0 = Wsm + kbase*32 + 4*n2 (splatted pairs); Asm staging [64][64]
template<int CHUNKS>
__device__ __forceinline__ void wres2(const float* __restrict__ AT,
                                      const float* __restrict__ wp0,
                                      float (*Asm)[64],
                                      int bp, int kl, int b4,
                                      ull& acc0, ull& acc1) {
    float4 pf0 = *(const float4*)&AT[(kl     ) * 64 + b4];
    float4 pf1 = *(const float4*)&AT[(kl + 16) * 64 + b4];
    float4 pf2 = *(const float4*)&AT[(kl + 32) * 64 + b4];
    float4 pf3 = *(const float4*)&AT[(kl + 48) * 64 + b4];
    for (int c = 0; c < CHUNKS; c++) {
        __syncthreads();
        *(float4*)&Asm[kl     ][b4] = pf0;
        *(float4*)&Asm[kl + 16][b4] = pf1;
        *(float4*)&Asm[kl + 32][b4] = pf2;
        *(float4*)&Asm[kl + 48][b4] = pf3;
        __syncthreads();
        if (c < CHUNKS - 1) {
            const float* src = AT + (c + 1) * 4096;
            pf0 = *(const float4*)&src[(kl     ) * 64 + b4];
            pf1 = *(const float4*)&src[(kl + 16) * 64 + b4];
            pf2 = *(const float4*)&src[(kl + 32) * 64 + b4];
            pf3 = *(const float4*)&src[(kl + 48) * 64 + b4];
        }
        const float* wp = wp0 + c * 64 * 32;
        #pragma unroll
        for (int k = 0; k < 64; k++) {
            ull a = *(const ull*)&Asm[k][2 * bp];
            ulonglong2 wv = *(const ulonglong2*)(wp + k * 32);
            acc0 = fma2(a, wv.x, acc0);
            acc1 = fma2(a, wv.y, acc1);
        }
    }
}

// merged-fill variant: A element = P0*c0 + P1*c1 (flash-softmax ctx merge)
template<int CHUNKS>
__device__ __forceinline__ void wres2m(const float* __restrict__ P0,
                                       const float* __restrict__ P1,
                                       float4 c0, float4 c1,
                                       const float* __restrict__ wp0,
                                       float (*Asm)[64],
                                       int bp, int kl, int b4,
                                       ull& acc0, ull& acc1) {
    #define MLD(off) ({ float4 x0 = *(const float4*)&P0[off]; \
                        float4 x1 = *(const float4*)&P1[off]; \
                        float4 r; \
                        r.x = x0.x * c0.x + x1.x * c1.x; \
                        r.y = x0.y * c0.y + x1.y * c1.y; \
                        r.z = x0.z * c0.z + x1.z * c1.z; \
                        r.w = x0.w * c0.w + x1.w * c1.w; r; })
    float4 pf0 = MLD((kl     ) * 64 + b4);
    float4 pf1 = MLD((kl + 16) * 64 + b4);
    float4 pf2 = MLD((kl + 32) * 64 + b4);
    float4 pf3 = MLD((kl + 48) * 64 + b4);
    for (int c = 0; c < CHUNKS; c++) {
        __syncthreads();
        *(float4*)&Asm[kl     ][b4] = pf0;
        *(float4*)&Asm[kl + 16][b4] = pf1;
        *(float4*)&Asm[kl + 32][b4] = pf2;
        *(float4*)&Asm[kl + 48][b4] = pf3;
        __syncthreads();
        if (c < CHUNKS - 1) {
            int base = (c + 1) * 4096;
            pf0 = MLD(base + (kl     ) * 64 + b4);
            pf1 = MLD(base + (kl + 16) * 64 + b4);
            pf2 = MLD(base + (kl + 32) * 64 + b4);
            pf3 = MLD(base + (kl + 48) * 64 + b4);
        }
        const float* wp = wp0 + c * 64 * 32;
        #pragma unroll
        for (int k = 0; k < 64; k++) {
            ull a = *(const ull*)&Asm[k][2 * bp];
            ulonglong2 wv = *(const ulonglong2*)(wp + k * 32);
            acc0 = fma2(a, wv.x, acc0);
            acc1 = fma2(a, wv.y, acc1);
        }
    }
    #undef MLD
}

// ---------------- persistent encoder ----------------
#define SMEM_ENC ((HH * 32 + 64 * 64) * 4)   // 48KB: splatted Wsm + Asm
__global__ void __launch_bounds__(256, 1) enc_persist() {
    extern __shared__ __align__(16) float dyn[];
    float* Wsm = dyn;                          // [256*32] splatted
    float (*Asm)[64] = (float(*)[64])(dyn + HH * 32);
    __shared__ float gsm[16][64];
    int blk = blockIdx.x, tid = threadIdx.x;
    int dir = blk >> 6, ub = blk & 63;
    for (int i = tid; i < 16 * HH; i += 256) {
        int r = i >> 8, k = i & 255;
        float v = g_Whhp[((size_t)dir * G4H + ub * 16 + r) * HH + k];
        int base = k * 32 + (r >> 1) * 4 + (r & 1) * 2;
        Wsm[base] = v; Wsm[base + 1] = v;
    }
    __syncthreads();
    int n2 = tid >> 5, bp = tid & 31;
    int kl = tid >> 4, b4 = (tid & 15) << 2;
    int uu = tid >> 6, bc = tid & 63;
    const float* wp0 = Wsm + 4 * n2;
    int p = 0;
    for (int t = 0; t < SS; t++) {
        const float* AT = g_hencT + ((size_t)p * 2 + dir) * HH * BB;
        ull acc0 = 0ull, acc1 = 0ull;
        wres2<4>(AT, wp0, Asm, bp, kl, b4, acc0, acc1);
        int s0 = dir ? (SS - 1 - t) : t;
        const float* gx = (dir ? g_gxb : g_gxf) + ((size_t)s0 * G4H + ub * 16) * 64;
        float2 a0 = unpack2(acc0), a1 = unpack2(acc1);
        float2 g0 = *(const float2*)&gx[(2 * n2) * 64 + 2 * bp];
        float2 g1 = *(const float2*)&gx[(2 * n2 + 1) * 64 + 2 * bp];
        *(float2*)&gsm[2 * n2][2 * bp]     = make_float2(a0.x + g0.x, a0.y + g0.y);
        *(float2*)&gsm[2 * n2 + 1][2 * bp] = make_float2(a1.x + g1.x, a1.y + g1.y);
        __syncthreads();
        {
            float gi = gsm[uu][bc], gf = gsm[4 + uu][bc], gg = gsm[8 + uu][bc], go = gsm[12 + uu][bc];
            int u = ub * 4 + uu;
            size_t ci = ((size_t)dir * HH + u) * BB + bc;
            float c = g_cencT[ci];
            c = sigf(gf) * c + sigf(gi) * tanhf(gg);
            float hn = sigf(go) * tanhf(c);
            g_cencT[ci] = c;
            g_hencT[((size_t)(p ^ 1) * 2 + dir) * HH * BB + (size_t)u * BB + bc] = hn;
            g_h[((size_t)s0 * BB + bc) * DHH + dir * HH + u] = hn;
        }
        p ^= 1;
        gsync(NBE);
    }
}

// ---------------- persistent decoder ----------------
#define SMEM_DEC ((1024 * 32 + 64 * 64) * 4)   // 144KB: splatted Wsm + Asm
__global__ void __launch_bounds__(256, 1) dec_persist(int l0, int l1) {
    extern __shared__ __align__(16) float dyn[];
    float* Wsm = dyn;                           // [1024*32] splatted
    float (*Asm)[64] = (float(*)[64])(dyn + 1024 * 32);
    __shared__ float gsm[16][64];
    __shared__ __align__(16) float hd_s[DHH];
    __shared__ float sc[64];
    __shared__ float red[64];
    __shared__ __align__(16) float c0sm[64], c1sm[64];
    int blk = blockIdx.x, tid = threadIdx.x;
    int half = blk & 1, ab = blk >> 1;          // attention: 2 blocks per batch
    for (int i = tid; i < 16 * 1024; i += 256) {
        int r = i >> 10, k = i & 1023;
        float v = g_Wcat[((size_t)blk * 16 + r) * 1024 + k];
        int base = k * 32 + (r >> 1) * 4 + (r & 1) * 2;
        Wsm[base] = v; Wsm[base + 1] = v;
    }
    __syncthreads();
    int n2 = tid >> 5, bp = tid & 31;
    int kl = tid >> 4, b4 = (tid & 15) << 2;
    int uu = tid >> 6, bc = tid & 63;
    const float* wpA = Wsm + 512 * 32 + 4 * n2;   // hd half (k 512..1023)
    const float* wpB = Wsm + 4 * n2;              // ctx half (k 0..511)
    int warp = tid >> 5, lane = tid & 31;
    for (int lvl = l0; lvl < l1; lvl++) {
        const float* pre = (lvl == 0) ? g_pre0 : g_pre1;
        float oh0 = g_ohcp[lvl * GD + blk * 16 + 2 * n2];
        float oh1 = g_ohcp[lvl * GD + blk * 16 + 2 * n2 + 1];
        for (int t = 0; t < SS; t++) {
            ull acc0 = 0ull, acc1 = 0ull;
            // ===== phase A: hd-half GEMM + attention half (all blocks) =====
            wres2<8>(g_hdT, wpA, Asm, bp, kl, b4, acc0, acc1);
            {
                for (int i = tid; i < DHH; i += 256) hd_s[i] = g_hd[ab * DHH + i];
                __syncthreads();
                // scores for 64 s values of this half
                #pragma unroll
                for (int it = 0; it < 2; it++) {
                    int s_loc = warp * 8 + it * 4 + (lane >> 3);   // hmm -- keep simple 8/warp
                }
                for (int it = 0; it < 8; it++) {
                    int s_loc = warp * 8 + it;
                    int s = half * 64 + s_loc;
                    const float4* w4 = (const float4*)(g_wh + ((size_t)s * BB + ab) * DHH);
                    const float4* h4 = (const float4*)hd_s;
                    float sum = 0.f;
                    #pragma unroll
                    for (int qq = 0; qq < 4; qq++) {
                        float4 a = w4[lane * 4 + qq];
                        float4 c = h4[lane * 4 + qq];
                        sum += a.x * c.x + a.y * c.y + a.z * c.z + a.w * c.w;
                    }
                    #pragma unroll
                    for (int off = 16; off; off >>= 1) sum += __shfl_xor_sync(0xffffffffu, sum, off);
                    if (lane == 0) sc[s_loc] = sum;
                }
                __syncthreads();
                if (tid < 64) red[tid] = sc[tid];
                __syncthreads();
                for (int off = 32; off; off >>= 1) {
                    if (tid < off) red[tid] = fmaxf(red[tid], red[tid + off]);
                    __syncthreads();
                }
                float mx = red[0];
                __syncthreads();
                if (tid < 64) { float e = __expf(sc[tid] - mx); sc[tid] = e; red[tid] = e; }
                __syncthreads();
                for (int off = 32; off; off >>= 1) {
                    if (tid < off) red[tid] += red[tid + off];
                    __syncthreads();
                }
                if (tid == 0) { g_attM[ab * 2 + half] = mx; g_attS[ab * 2 + half] = red[0]; }
                // partial unnormalized ctx over this half's 64 s
                for (int d = tid; d < DHH; d += 256) {
                    float acc = 0.f;
                    #pragma unroll 8
                    for (int s_loc = 0; s_loc < 64; s_loc++)
                        acc += sc[s_loc] * g_h[(((size_t)(half * 64 + s_loc)) * BB + ab) * DHH + d];
                    g_ctxP[((size_t)half * DHH + d) * 64 + ab] = acc;
                }
            }
            gsync(NBD);
            // ===== phase B: flash-merge + ctx-half GEMM + cell =====
            if (tid < 64) {
                float m0 = g_attM[tid * 2], m1 = g_attM[tid * 2 + 1];
                float M = fmaxf(m0, m1);
                float e0 = __expf(m0 - M), e1 = __expf(m1 - M);
                float den = g_attS[tid * 2] * e0 + g_attS[tid * 2 + 1] * e1;
                c0sm[tid] = e0 / den;
                c1sm[tid] = e1 / den;
            }
            __syncthreads();
            float4 c0v = *(const float4*)&c0sm[b4];
            float4 c1v = *(const float4*)&c1sm[b4];
            wres2m<8>(g_ctxP, g_ctxP + DHH * 64, c0v, c1v, wpB, Asm, bp, kl, b4, acc0, acc1);
            {
                const float* pr = pre + ((size_t)t * GD + blk * 16) * 64;
                float2 a0 = unpack2(acc0), a1 = unpack2(acc1);
                float2 p0 = *(const float2*)&pr[(2 * n2) * 64 + 2 * bp];
                float2 p1 = *(const float2*)&pr[(2 * n2 + 1) * 64 + 2 * bp];
                *(float2*)&gsm[2 * n2][2 * bp]     = make_float2(a0.x + p0.x + oh0, a0.y + p0.y + oh0);
                *(float2*)&gsm[2 * n2 + 1][2 * bp] = make_float2(a1.x + p1.x + oh1, a1.y + p1.y + oh1);
            }
            __syncthreads();
            {
                float gi = gsm[uu][bc], gf = gsm[4 + uu][bc], gg = gsm[8 + uu][bc], go = gsm[12 + uu][bc];
                int u = blk * 4 + uu;
                size_t ci = (size_t)u * BB + bc;
                float c = g_cdT[ci];
                c = sigf(gf) * c + sigf(gi) * tanhf(gg);
                float hn = sigf(go) * tanhf(c);
                g_cdT[ci] = c;
                g_hdT[ci] = hn;
                g_hd[(size_t)bc * DHH + u] = hn;
                g_dout[(((size_t)lvl * SS + t) * BB + bc) * DHH + u] = hn;
            }
            gsync(NBD);
        }
    }
}

// ---------------- output projection ----------------
__global__ void out_proj(const float* __restrict__ W2, const float* __restrict__ b2,
                         float* __restrict__ out) {
    int m = blockIdx.x;
    int lane = threadIdx.x;
    const float* drow = g_dout + (size_t)m * DHH;
    float acc[CC] = {};
    for (int k = lane; k < DHH; k += 32) {
        float d = drow[k];
        #pragma unroll
        for (int c = 0; c < CC; c++) acc[c] += d * W2[c * DHH + k];
    }
    #pragma unroll
    for (int c = 0; c < CC; c++) {
        float v = acc[c];
        #pragma unroll
        for (int off = 16; off; off >>= 1) v += __shfl_xor_sync(0xffffffffu, v, off);
        if (lane == 0) out[(size_t)m * CC + c] = v + b2[c];
    }
}

// ---------------- host ----------------
extern "C" void kernel_launch(void* const* d_in, const int* in_sizes, int n_in,
                              void* d_out, int out_size) {
    const int*   seqs  = (const int*)d_in[0];
    const float* emb   = (const float*)d_in[2];
    const float* Wih_f = (const float*)d_in[3];
    const float* Whh_f = (const float*)d_in[4];
    const float* bih_f = (const float*)d_in[5];
    const float* bhh_f = (const float*)d_in[6];
    const float* Wih_b = (const float*)d_in[7];
    const float* Whh_b = (const float*)d_in[8];
    const float* bih_b = (const float*)d_in[9];
    const float* bhh_b = (const float*)d_in[10];
    const float* Wl    = (const float*)d_in[11];
    const float* Wih_d = (const float*)d_in[12];
    const float* Whh_d = (const float*)d_in[13];
    const float* bih_d = (const float*)d_in[14];
    const float* bhh_d = (const float*)d_in[15];
    const float* W2    = (const float*)d_in[16];
    const float* b2    = (const float*)d_in[17];
    float* out = (float*)d_out;

    cudaFuncSetAttribute(enc_persist, cudaFuncAttributeMaxDynamicSharedMemorySize, SMEM_ENC);
    cudaFuncSetAttribute(dec_persist, cudaFuncAttributeMaxDynamicSharedMemorySize, SMEM_DEC);

    // 0: prep
    k_prep<<<(PREP_TOTAL + 255) / 256, 256>>>(Whh_f, Whh_b, Wih_f, Wih_b,
                                              bih_f, bhh_f, bih_b, bhh_b,
                                              Wih_d, Whh_d, bih_d, bhh_d);
    // 1: embed
    k_embed<<<SS * BB, 128>>>(seqs, emb);
    // 2: encoder input GEMMs (both dirs, transposed out)
    k_encg<<<dim3(SS * BB / 64, G4H / 64, 2), 256>>>();
    // 3: encoder recurrence
    enc_persist<<<NBE, 256, SMEM_ENC>>>();
    // 4: pre0 (+bias, transposed) and wh, one launch
    k_pre<<<dim3(SS * BB / 64, 40), 256>>>(Wl);
    // 5: decoder level 0  <-- ncu -s 5 target
    dec_persist<<<NBD, 256, SMEM_DEC>>>(0, 1);
    // 6: pre1 = pre0 + (dout0 - h)@Wprev
    k_pre1<<<dim3(SS * BB / 64, GD / 64), 256>>>();
    // 7: decoder levels 1-3
    dec_persist<<<NBD, 256, SMEM_DEC>>>(1, 4);
    // 8: logits
    out_proj<<<LMAXX * SS * BB, 32>>>(W2, b2, out);
}

// round 12
// speedup vs baseline: 2.3343x; 1.0035x over previous
#include <cuda_runtime.h>
#include <math.h>

// ---------------- problem dims ----------------
#define SS    128
#define BB    64
#define EE    512
#define HH    256
#define DHH   512
#define G4H   1024
#define GD    2048
#define LDWD  2052
#define LMAXX 4
#define CC    9

#define NBE   128
#define NBD   128

typedef unsigned long long ull;

// gate-locality permutations: block owns all 4 gates of 4 units
__device__ __forceinline__ int enperm(int np) { return (((np >> 2) & 3) << 8) + ((np >> 4) << 2) + (np & 3); }
__device__ __forceinline__ int deperm(int np) { return (((np >> 2) & 3) << 9) + ((np >> 4) << 2) + (np & 3); }

// ---------------- static device scratch ----------------
__device__ float g_x   [SS*BB*EE];
__device__ float g_gxf [SS*BB*G4H];      // TRANSPOSED: [s][np][b]
__device__ float g_gxb [SS*BB*G4H];      // TRANSPOSED: [s][np][b]
__device__ float g_h   [SS*BB*DHH];      // [s][b][d] row-major
__device__ float g_wh  [SS*BB*DHH];      // [s][b][d] row-major
__device__ float g_pre0[SS*BB*GD];       // TRANSPOSED: [t][np][b]
__device__ float g_pre1[SS*BB*GD];       // TRANSPOSED: [t][np][b]
__device__ float g_dout[LMAXX*SS*BB*DHH];// [lvl][t][b][u]
__device__ float g_hencT[2*2*HH*BB];     // [p][dir][u][b]
__device__ float g_cencT[2*HH*BB];
__device__ float g_hd  [BB*DHH];         // [b][u] (attention reads)
__device__ float g_hdT [DHH*BB];         // [u][b] (GEMM k-major)
__device__ float g_cdT [DHH*BB];
__device__ float g_ctxP[2*DHH*BB];       // [half][d][b] unnormalized partial ctx
__device__ float g_attM[2*BB];           // [b*2+half] local max
__device__ float g_attS[2*BB];           // [b*2+half] local sum
__device__ float g_Whhp[2*G4H*HH];       // permuted rows [dir][np][k]
__device__ float g_Wihp[2*G4H*EE];
__device__ float g_bep [2*G4H];
__device__ float g_Wcat[GD*1024];        // permuted rows: [Wih_d[:, :512] | Whh_d]
__device__ float g_Wmid0[GD*1024];       // permuted rows: Wih_d[:,512:1536] with h-cols += Wprev
__device__ float g_Wprev[GD*DHH];        // permuted rows: Wih_d[:, 1536:2048]
__device__ float g_bdp [GD];
__device__ float g_ohcp[LMAXX*GD];

// ---------------- flag-tree grid barrier (no atomic storm, nanosleep backoff) ----------------
__device__ unsigned g_flags[NBD * 32];   // one flag per block, own 128B line
__device__ unsigned g_rel;               // release word (monotonic generation)

__device__ __forceinline__ unsigned bar_base() {
    unsigned v;
    asm volatile("ld.global.u32 %0, [%1];" : "=r"(v) : "l"(&g_rel));
    return v;
}

__device__ __forceinline__ void gsync2(int blk, unsigned gen) {
    __syncthreads();
    if (threadIdx.x == 0)
        asm volatile("st.release.gpu.u32 [%0], %1;" :: "l"(&g_flags[blk * 32]), "r"(gen) : "memory");
    if (blk == 0) {
        if (threadIdx.x < NBD) {
            unsigned v;
            while (true) {
                asm volatile("ld.acquire.gpu.u32 %0, [%1];" : "=r"(v) : "l"(&g_flags[threadIdx.x * 32]) : "memory");
                if ((int)(v - gen) >= 0) break;
                __nanosleep(64);
            }
        }
        __syncthreads();
        if (threadIdx.x == 0)
            asm volatile("st.release.gpu.u32 [%0], %1;" :: "l"(&g_rel), "r"(gen) : "memory");
    } else if (threadIdx.x == 0) {
        unsigned v;
        while (true) {
            asm volatile("ld.acquire.gpu.u32 %0, [%1];" : "=r"(v) : "l"(&g_rel) : "memory");
            if ((int)(v - gen) >= 0) break;
            __nanosleep(64);
        }
    }
    __syncthreads();
}

__device__ __forceinline__ float sigf(float x) { return 1.0f / (1.0f + __expf(-x)); }

// packed f32x2 FMA (SASS FFMA2: 2 MACs/instr)
__device__ __forceinline__ ull fma2(ull a, ull b, ull c) {
    ull d;
    asm("fma.rn.f32x2 %0, %1, %2, %3;" : "=l"(d) : "l"(a), "l"(b), "l"(c));
    return d;
}
__device__ __forceinline__ float2 unpack2(ull v) {
    float2 r;
    asm("mov.b64 {%0, %1}, %2;" : "=f"(r.x), "=f"(r.y) : "l"(v));
    return r;
}

// ---------------- prep ----------------
#define Z_TOTAL 196608
#define PREP_TOTAL (Z_TOTAL + 524288 + 1048576 + 2048 + 2097152 + 2097152 + 1048576 + 2048 + 8192)
__global__ void k_prep(const float* __restrict__ Whh_f, const float* __restrict__ Whh_b,
                       const float* __restrict__ Wih_f, const float* __restrict__ Wih_b,
                       const float* __restrict__ bih_f, const float* __restrict__ bhh_f,
                       const float* __restrict__ bih_b, const float* __restrict__ bhh_b,
                       const float* __restrict__ Wih_d, const float* __restrict__ Whh_d,
                       const float* __restrict__ bih_d, const float* __restrict__ bhh_d) {
    long long i = (long long)blockIdx.x * 256 + threadIdx.x;
    if (i < Z_TOTAL) {
        if (i < 65536) g_hencT[i] = 0.f;
        else if (i < 98304) g_cencT[i - 65536] = 0.f;
        else if (i < 131072) g_hd[i - 98304] = 0.f;
        else if (i < 163840) g_hdT[i - 131072] = 0.f;
        else g_cdT[i - 163840] = 0.f;
        return;
    }
    i -= Z_TOTAL;
    if (i < 524288) { // Whhp
        int dir = (int)(i >> 18), r = (int)(i & 262143);
        int np = r >> 8, k = r & 255;
        int n = enperm(np);
        g_Whhp[i] = (dir ? Whh_b : Whh_f)[n * HH + k];
        return;
    }
    i -= 524288;
    if (i < 1048576) { // Wihp
        int dir = (int)(i >> 19), r = (int)(i & 524287);
        int np = r >> 9, k = r & 511;
        int n = enperm(np);
        g_Wihp[i] = (dir ? Wih_b : Wih_f)[n * EE + k];
        return;
    }
    i -= 1048576;
    if (i < 2048) { // encoder bias
        int dir = (int)(i >> 10), np = (int)(i & 1023);
        int n = enperm(np);
        g_bep[i] = dir ? (bih_b[n] + bhh_b[n]) : (bih_f[n] + bhh_f[n]);
        return;
    }
    i -= 2048;
    if (i < 2097152) { // Wcat
        int np = (int)(i >> 10), k = (int)(i & 1023);
        int n = deperm(np);
        g_Wcat[i] = (k < 512) ? Wih_d[(size_t)n * LDWD + k] : Whh_d[(size_t)n * DHH + (k - 512)];
        return;
    }
    i -= 2097152;
    if (i < 2097152) { // Wmid0 = Wih_d[:,512:1536] with first 512 k-cols += Wprev
        int np = (int)(i >> 10), k = (int)(i & 1023);
        int n = deperm(np);
        float v = Wih_d[(size_t)n * LDWD + 512 + k];
        if (k < 512) v += Wih_d[(size_t)n * LDWD + 1536 + k];
        g_Wmid0[i] = v;
        return;
    }
    i -= 2097152;
    if (i < 1048576) { // Wprev
        int np = (int)(i >> 9), k = (int)(i & 511);
        int n = deperm(np);
        g_Wprev[i] = Wih_d[(size_t)n * LDWD + 1536 + k];
        return;
    }
    i -= 1048576;
    if (i < 2048) { // decoder bias
        int n = deperm((int)i);
        g_bdp[i] = bih_d[n] + bhh_d[n];
        return;
    }
    i -= 2048;
    if (i < 8192) { // one-hot columns
        int lvl = (int)(i >> 11), np = (int)(i & 2047);
        int n = deperm(np);
        g_ohcp[i] = Wih_d[(size_t)n * LDWD + GD + lvl];
        return;
    }
}

__global__ void k_embed(const int* __restrict__ seqs, const float* __restrict__ emb) {
    int m = blockIdx.x;            // m = s*64 + b
    int s0 = m >> 6, b = m & 63;
    int row = seqs[b * SS + s0];
    const float4* src = (const float4*)(emb + (size_t)row * EE);
    float4* dst = (float4*)(g_x + (size_t)m * EE);
    dst[threadIdx.x] = src[threadIdx.x];
}

// ---------------- precompute GEMM core (64x64 tiles, ~31 TF/s measured) ----------------
__device__ __forceinline__ void gemm_core(const float* __restrict__ A, int lda,
                        const float* __restrict__ A2, const float* __restrict__ Asub,
                        const float* __restrict__ W, int ldw,
                        float* __restrict__ C, int N, int K,
                        const float* __restrict__ add, const float* __restrict__ bias,
                        int tpose, int m0, int n0) {
    __shared__ __align__(16) float As[16][68];
    __shared__ __align__(16) float Ws[16][68];
    int tid = threadIdx.x;
    int tm = (tid >> 4) << 2, tn = (tid & 15) << 2;
    float acc[4][4] = {};
    for (int k0 = 0; k0 < K; k0 += 16) {
        const float* Asrc = A;
        int kk0 = k0;
        bool second = (A2 && k0 >= 512);
        if (second) { Asrc = A2; kk0 = k0 - 512; }
        #pragma unroll
        for (int i = tid; i < 1024; i += 256) {
            int r = i >> 4, k = i & 15;
            float v = Asrc[(size_t)(m0 + r) * lda + kk0 + k];
            if (Asub && !second) v -= Asub[(size_t)(m0 + r) * lda + kk0 + k];
            As[k][r] = v;
            Ws[k][r] = W[(size_t)(n0 + r) * ldw + k0 + k];
        }
        __syncthreads();
        #pragma unroll
        for (int k = 0; k < 16; k++) {
            float4 a4 = *(const float4*)&As[k][tm];
            float4 w4 = *(const float4*)&Ws[k][tn];
            acc[0][0] += a4.x * w4.x; acc[0][1] += a4.x * w4.y; acc[0][2] += a4.x * w4.z; acc[0][3] += a4.x * w4.w;
            acc[1][0] += a4.y * w4.x; acc[1][1] += a4.y * w4.y; acc[1][2] += a4.y * w4.z; acc[1][3] += a4.y * w4.w;
            acc[2][0] += a4.z * w4.x; acc[2][1] += a4.z * w4.y; acc[2][2] += a4.z * w4.z; acc[2][3] += a4.z * w4.w;
            acc[3][0] += a4.w * w4.x; acc[3][1] += a4.w * w4.y; acc[3][2] += a4.w * w4.z; acc[3][3] += a4.w * w4.w;
        }
        __syncthreads();
    }
    #pragma unroll
    for (int i = 0; i < 4; i++)
        #pragma unroll
        for (int j = 0; j < 4; j++) {
            int m = m0 + tm + i, n = n0 + tn + j;
            float v = acc[i][j];
            if (bias) v += bias[n];
            if (tpose) {
                size_t idx = ((size_t)(m >> 6) * N + n) * 64 + (m & 63);
                if (add) v += add[idx];
                C[idx] = v;
            } else {
                size_t idx = (size_t)m * N + n;
                if (add) v += add[idx];
                C[idx] = v;
            }
        }
}

__global__ void __launch_bounds__(256) k_encg() {
    int z = blockIdx.z;
    gemm_core(g_x, EE, nullptr, nullptr,
              g_Wihp + (size_t)z * G4H * EE, EE,
              z ? g_gxb : g_gxf, G4H, EE,
              nullptr, g_bep + z * G4H, 1,
              blockIdx.x * 64, blockIdx.y * 64);
}

__global__ void __launch_bounds__(256) k_pre(const float* __restrict__ Wl) {
    if (blockIdx.y < 32) {
        gemm_core(g_h, DHH, g_x, nullptr, g_Wmid0, 1024, g_pre0, GD, 1024,
                  nullptr, g_bdp, 1, blockIdx.x * 64, blockIdx.y * 64);
    } else {
        gemm_core(g_h, DHH, nullptr, nullptr, Wl, DHH, g_wh, DHH, DHH,
                  nullptr, nullptr, 0, blockIdx.x * 64, (blockIdx.y - 32) * 64);
    }
}

__global__ void __launch_bounds__(256) k_pre1() {
    gemm_core(g_dout, DHH, nullptr, g_h, g_Wprev, DHH, g_pre1, GD, DHH,
              g_pre0, nullptr, 1, blockIdx.x * 64, blockIdx.y * 64);
}

// ---------------- W-resident f32x2 GEMM half ----------------
// AT: [K][64] k-major; wp0 = Wsm + kbase*32 + 4*np (splatted pairs); Asm staging [64][64]
// Warp map: np = (lane>>2), bp = warp*4 + (lane&3)  -> A-reads dedup to 32B/warp-k
template<int CHUNKS>
__device__ __forceinline__ void wres2(const float* __restrict__ AT,
                                      const float* __restrict__ wp0,
                                      float (*Asm)[64],
                                      int bp, int kl, int b4,
                                      ull& acc0, ull& acc1) {
    float4 pf0 = *(const float4*)&AT[(kl     ) * 64 + b4];
    float4 pf1 = *(const float4*)&AT[(kl + 16) * 64 + b4];
    float4 pf2 = *(const float4*)&AT[(kl + 32) * 64 + b4];
    float4 pf3 = *(const float4*)&AT[(kl + 48) * 64 + b4];
    for (int c = 0; c < CHUNKS; c++) {
        __syncthreads();
        *(float4*)&Asm[kl     ][b4] = pf0;
        *(float4*)&Asm[kl + 16][b4] = pf1;
        *(float4*)&Asm[kl + 32][b4] = pf2;
        *(float4*)&Asm[kl + 48][b4] = pf3;
        __syncthreads();
        if (c < CHUNKS - 1) {
            const float* src = AT + (c + 1) * 4096;
            pf0 = *(const float4*)&src[(kl     ) * 64 + b4];
            pf1 = *(const float4*)&src[(kl + 16) * 64 + b4];
            pf2 = *(const float4*)&src[(kl + 32) * 64 + b4];
            pf3 = *(const float4*)&src[(kl + 48) * 64 + b4];
        }
        const float* wp = wp0 + c * 64 * 32;
        #pragma unroll
        for (int k = 0; k < 64; k++) {
            ull a = *(const ull*)&Asm[k][2 * bp];
            ulonglong2 wv = *(const ulonglong2*)(wp + k * 32);
            acc0 = fma2(a, wv.x, acc0);
            acc1 = fma2(a, wv.y, acc1);
        }
    }
}

// merged-fill variant: A element = P0*c0 + P1*c1 (flash-softmax ctx merge)
template<int CHUNKS>
__device__ __forceinline__ void wres2m(const float* __restrict__ P0,
                                       const float* __restrict__ P1,
                                       float4 c0, float4 c1,
                                       const float* __restrict__ wp0,
                                       float (*Asm)[64],
                                       int bp, int kl, int b4,
                                       ull& acc0, ull& acc1) {
    #define MLD(off) ({ float4 x0 = *(const float4*)&P0[off]; \
                        float4 x1 = *(const float4*)&P1[off]; \
                        float4 r; \
                        r.x = x0.x * c0.x + x1.x * c1.x; \
                        r.y = x0.y * c0.y + x1.y * c1.y; \
                        r.z = x0.z * c0.z + x1.z * c1.z; \
                        r.w = x0.w * c0.w + x1.w * c1.w; r; })
    float4 pf0 = MLD((kl     ) * 64 + b4);
    float4 pf1 = MLD((kl + 16) * 64 + b4);
    float4 pf2 = MLD((kl + 32) * 64 + b4);
    float4 pf3 = MLD((kl + 48) * 64 + b4);
    for (int c = 0; c < CHUNKS; c++) {
        __syncthreads();
        *(float4*)&Asm[kl     ][b4] = pf0;
        *(float4*)&Asm[kl + 16][b4] = pf1;
        *(float4*)&Asm[kl + 32][b4] = pf2;
        *(float4*)&Asm[kl + 48][b4] = pf3;
        __syncthreads();
        if (c < CHUNKS - 1) {
            int base = (c + 1) * 4096;
            pf0 = MLD(base + (kl     ) * 64 + b4);
            pf1 = MLD(base + (kl + 16) * 64 + b4);
            pf2 = MLD(base + (kl + 32) * 64 + b4);
            pf3 = MLD(base + (kl + 48) * 64 + b4);
        }
        const float* wp = wp0 + c * 64 * 32;
        #pragma unroll
        for (int k = 0; k < 64; k++) {
            ull a = *(const ull*)&Asm[k][2 * bp];
            ulonglong2 wv = *(const ulonglong2*)(wp + k * 32);
            acc0 = fma2(a, wv.x, acc0);
            acc1 = fma2(a, wv.y, acc1);
        }
    }
    #undef MLD
}

// ---------------- persistent encoder ----------------
#define SMEM_ENC ((HH * 32 + 64 * 64) * 4)   // 48KB: splatted Wsm + Asm
__global__ void __launch_bounds__(256, 1) enc_persist() {
    extern __shared__ __align__(16) float dyn[];
    float* Wsm = dyn;                          // [256*32] splatted
    float (*Asm)[64] = (float(*)[64])(dyn + HH * 32);
    __shared__ float gsm[16][64];
    int blk = blockIdx.x, tid = threadIdx.x;
    int dir = blk >> 6, ub = blk & 63;
    for (int i = tid; i < 16 * HH; i += 256) {
        int r = i >> 8, k = i & 255;
        float v = g_Whhp[((size_t)dir * G4H + ub * 16 + r) * HH + k];
        int base = k * 32 + (r >> 1) * 4 + (r & 1) * 2;
        Wsm[base] = v; Wsm[base + 1] = v;
    }
    __syncthreads();
    int lane = tid & 31, w = tid >> 5;
    int np = lane >> 2, bp = w * 4 + (lane & 3);
    int kl = tid >> 4, b4 = (tid & 15) << 2;
    int uu = tid >> 6, bc = tid & 63;
    const float* wp0 = Wsm + 4 * np;
    unsigned gen = bar_base();
    int p = 0;
    for (int t = 0; t < SS; t++) {
        const float* AT = g_hencT + ((size_t)p * 2 + dir) * HH * BB;
        ull acc0 = 0ull, acc1 = 0ull;
        wres2<4>(AT, wp0, Asm, bp, kl, b4, acc0, acc1);
        int s0 = dir ? (SS - 1 - t) : t;
        const float* gx = (dir ? g_gxb : g_gxf) + ((size_t)s0 * G4H + ub * 16) * 64;
        float2 a0 = unpack2(acc0), a1 = unpack2(acc1);
        float2 g0 = *(const float2*)&gx[(2 * np) * 64 + 2 * bp];
        float2 g1 = *(const float2*)&gx[(2 * np + 1) * 64 + 2 * bp];
        *(float2*)&gsm[2 * np][2 * bp]     = make_float2(a0.x + g0.x, a0.y + g0.y);
        *(float2*)&gsm[2 * np + 1][2 * bp] = make_float2(a1.x + g1.x, a1.y + g1.y);
        __syncthreads();
        {
            float gi = gsm[uu][bc], gf = gsm[4 + uu][bc], gg = gsm[8 + uu][bc], go = gsm[12 + uu][bc];
            int u = ub * 4 + uu;
            size_t ci = ((size_t)dir * HH + u) * BB + bc;
            float c = g_cencT[ci];
            c = sigf(gf) * c + sigf(gi) * tanhf(gg);
            float hn = sigf(go) * tanhf(c);
            g_cencT[ci] = c;
            g_hencT[((size_t)(p ^ 1) * 2 + dir) * HH * BB + (size_t)u * BB + bc] = hn;
            g_h[((size_t)s0 * BB + bc) * DHH + dir * HH + u] = hn;
        }
        p ^= 1;
        gsync2(blk, ++gen);
    }
}

// ---------------- persistent decoder ----------------
#define SMEM_DEC ((1024 * 32 + 64 * 64) * 4)   // 144KB: splatted Wsm + Asm
__global__ void __launch_bounds__(256, 1) dec_persist(int l0, int l1) {
    extern __shared__ __align__(16) float dyn[];
    float* Wsm = dyn;                           // [1024*32] splatted
    float (*Asm)[64] = (float(*)[64])(dyn + 1024 * 32);
    __shared__ float gsm[16][64];
    __shared__ __align__(16) float hd_s[DHH];
    __shared__ float sc[64];
    __shared__ float red[64];
    __shared__ __align__(16) float c0sm[64], c1sm[64];
    int blk = blockIdx.x, tid = threadIdx.x;
    int half = blk & 1, ab = blk >> 1;          // attention: 2 blocks per batch
    for (int i = tid; i < 16 * 1024; i += 256) {
        int r = i >> 10, k = i & 1023;
        float v = g_Wcat[((size_t)blk * 16 + r) * 1024 + k];
        int base = k * 32 + (r >> 1) * 4 + (r & 1) * 2;
        Wsm[base] = v; Wsm[base + 1] = v;
    }
    __syncthreads();
    int lane = tid & 31, w = tid >> 5;
    int np = lane >> 2, bp = w * 4 + (lane & 3);
    int kl = tid >> 4, b4 = (tid & 15) << 2;
    int uu = tid >> 6, bc = tid & 63;
    const float* wpA = Wsm + 512 * 32 + 4 * np;   // hd half (k 512..1023)
    const float* wpB = Wsm + 4 * np;              // ctx half (k 0..511)
    unsigned gen = bar_base();
    for (int lvl = l0; lvl < l1; lvl++) {
        const float* pre = (lvl == 0) ? g_pre0 : g_pre1;
        float oh0 = g_ohcp[lvl * GD + blk * 16 + 2 * np];
        float oh1 = g_ohcp[lvl * GD + blk * 16 + 2 * np + 1];
        for (int t = 0; t < SS; t++) {
            // ===== phase A: attention half first (L2-bound), then hd-half GEMM =====
            {
                for (int i = tid; i < DHH; i += 256) hd_s[i] = g_hd[ab * DHH + i];
                __syncthreads();
                for (int it = 0; it < 8; it++) {
                    int s_loc = w * 8 + it;
                    int s = half * 64 + s_loc;
                    const float4* w4 = (const float4*)(g_wh + ((size_t)s * BB + ab) * DHH);
                    const float4* h4 = (const float4*)hd_s;
                    float sum = 0.f;
                    #pragma unroll
                    for (int qq = 0; qq < 4; qq++) {
                        float4 a = w4[lane * 4 + qq];
                        float4 c = h4[lane * 4 + qq];
                        sum += a.x * c.x + a.y * c.y + a.z * c.z + a.w * c.w;
                    }
                    #pragma unroll
                    for (int off = 16; off; off >>= 1) sum += __shfl_xor_sync(0xffffffffu, sum, off);
                    if (lane == 0) sc[s_loc] = sum;
                }
                __syncthreads();
                if (tid < 64) red[tid] = sc[tid];
                __syncthreads();
                for (int off = 32; off; off >>= 1) {
                    if (tid < off) red[tid] = fmaxf(red[tid], red[tid + off]);
                    __syncthreads();
                }
                float mx = red[0];
                __syncthreads();
                if (tid < 64) { float e = __expf(sc[tid] - mx); sc[tid] = e; red[tid] = e; }
                __syncthreads();
                for (int off = 32; off; off >>= 1) {
                    if (tid < off) red[tid] += red[tid + off];
                    __syncthreads();
                }
                if (tid == 0) { g_attM[ab * 2 + half] = mx; g_attS[ab * 2 + half] = red[0]; }
                // partial unnormalized ctx over this half's 64 s
                for (int d = tid; d < DHH; d += 256) {
                    float acc = 0.f;
                    #pragma unroll 8
                    for (int s_loc = 0; s_loc < 64; s_loc++)
                        acc += sc[s_loc] * g_h[(((size_t)(half * 64 + s_loc)) * BB + ab) * DHH + d];
                    g_ctxP[((size_t)half * DHH + d) * 64 + ab] = acc;
                }
                __syncthreads();
            }
            ull acc0 = 0ull, acc1 = 0ull;
            wres2<8>(g_hdT, wpA, Asm, bp, kl, b4, acc0, acc1);
            gsync2(blk, ++gen);
            // ===== phase B: flash-merge + ctx-half GEMM + cell =====
            if (tid < 64) {
                float m0 = g_attM[tid * 2], m1 = g_attM[tid * 2 + 1];
                float M = fmaxf(m0, m1);
                float e0 = __expf(m0 - M), e1 = __expf(m1 - M);
                float den = g_attS[tid * 2] * e0 + g_attS[tid * 2 + 1] * e1;
                c0sm[tid] = e0 / den;
                c1sm[tid] = e1 / den;
            }
            __syncthreads();
            float4 c0v = *(const float4*)&c0sm[b4];
            float4 c1v = *(const float4*)&c1sm[b4];
            wres2m<8>(g_ctxP, g_ctxP + DHH * 64, c0v, c1v, wpB, Asm, bp, kl, b4, acc0, acc1);
            {
                const float* pr = pre + ((size_t)t * GD + blk * 16) * 64;
                float2 a0 = unpack2(acc0), a1 = unpack2(acc1);
                float2 p0 = *(const float2*)&pr[(2 * np) * 64 + 2 * bp];
                float2 p1 = *(const float2*)&pr[(2 * np + 1) * 64 + 2 * bp];
                *(float2*)&gsm[2 * np][2 * bp]     = make_float2(a0.x + p0.x + oh0, a0.y + p0.y + oh0);
                *(float2*)&gsm[2 * np + 1][2 * bp] = make_float2(a1.x + p1.x + oh1, a1.y + p1.y + oh1);
            }
            __syncthreads();
            {
                float gi = gsm[uu][bc], gf = gsm[4 + uu][bc], gg = gsm[8 + uu][bc], go = gsm[12 + uu][bc];
                int u = blk * 4 + uu;
                size_t ci = (size_t)u * BB + bc;
                float c = g_cdT[ci];
                c = sigf(gf) * c + sigf(gi) * tanhf(gg);
                float hn = sigf(go) * tanhf(c);
                g_cdT[ci] = c;
                g_hdT[ci] = hn;
                g_hd[(size_t)bc * DHH + u] = hn;
                g_dout[(((size_t)lvl * SS + t) * BB + bc) * DHH + u] = hn;
            }
            gsync2(blk, ++gen);
        }
    }
}

// ---------------- output projection ----------------
__global__ void out_proj(const float* __restrict__ W2, const float* __restrict__ b2,
                         float* __restrict__ out) {
    int m = blockIdx.x;
    int lane = threadIdx.x;
    const float* drow = g_dout + (size_t)m * DHH;
    float acc[CC] = {};
    for (int k = lane; k < DHH; k += 32) {
        float d = drow[k];
        #pragma unroll
        for (int c = 0; c < CC; c++) acc[c] += d * W2[c * DHH + k];
    }
    #pragma unroll
    for (int c = 0; c < CC; c++) {
        float v = acc[c];
        #pragma unroll
        for (int off = 16; off; off >>= 1) v += __shfl_xor_sync(0xffffffffu, v, off);
        if (lane == 0) out[(size_t)m * CC + c] = v + b2[c];
    }
}

// ---------------- host ----------------
extern "C" void kernel_launch(void* const* d_in, const int* in_sizes, int n_in,
                              void* d_out, int out_size) {
    const int*   seqs  = (const int*)d_in[0];
    const float* emb   = (const float*)d_in[2];
    const float* Wih_f = (const float*)d_in[3];
    const float* Whh_f = (const float*)d_in[4];
    const float* bih_f = (const float*)d_in[5];
    const float* bhh_f = (const float*)d_in[6];
    const float* Wih_b = (const float*)d_in[7];
    const float* Whh_b = (const float*)d_in[8];
    const float* bih_b = (const float*)d_in[9];
    const float* bhh_b = (const float*)d_in[10];
    const float* Wl    = (const float*)d_in[11];
    const float* Wih_d = (const float*)d_in[12];
    const float* Whh_d = (const float*)d_in[13];
    const float* bih_d = (const float*)d_in[14];
    const float* bhh_d = (const float*)d_in[15];
    const float* W2    = (const float*)d_in[16];
    const float* b2    = (const float*)d_in[17];
    float* out = (float*)d_out;

    cudaFuncSetAttribute(enc_persist, cudaFuncAttributeMaxDynamicSharedMemorySize, SMEM_ENC);
    cudaFuncSetAttribute(dec_persist, cudaFuncAttributeMaxDynamicSharedMemorySize, SMEM_DEC);

    // 0: prep
    k_prep<<<(PREP_TOTAL + 255) / 256, 256>>>(Whh_f, Whh_b, Wih_f, Wih_b,
                                              bih_f, bhh_f, bih_b, bhh_b,
                                              Wih_d, Whh_d, bih_d, bhh_d);
    // 1: embed
    k_embed<<<SS * BB, 128>>>(seqs, emb);
    // 2: encoder input GEMMs (both dirs, transposed out)
    k_encg<<<dim3(SS * BB / 64, G4H / 64, 2), 256>>>();
    // 3: encoder recurrence
    enc_persist<<<NBE, 256, SMEM_ENC>>>();
    // 4: pre0 (+bias, transposed) and wh, one launch
    k_pre<<<dim3(SS * BB / 64, 40), 256>>>(Wl);
    // 5: decoder level 0
    dec_persist<<<NBD, 256, SMEM_DEC>>>(0, 1);
    // 6: pre1 = pre0 + (dout0 - h)@Wprev
    k_pre1<<<dim3(SS * BB / 64, GD / 64), 256>>>();
    // 7: decoder levels 1-3
    dec_persist<<<NBD, 256, SMEM_DEC>>>(1, 4);
    // 8: logits
    out_proj<<<LMAXX * SS * BB, 32>>>(W2, b2, out);
}